// round 12
// baseline (speedup 1.0000x reference)
#include <cuda_runtime.h>
#include <cuda_bf16.h>
#include <math.h>
#include <stdint.h>

// ---------------------------------------------------------------------------
// Problem constants
// ---------------------------------------------------------------------------
#define MAXN 100000
#define MAXE 800000
#define MAXET (MAXE + MAXN)
#define F1 256
#define HH 8
#define OUTC 40

// ---------------------------------------------------------------------------
// Scratch
// ---------------------------------------------------------------------------
__device__ float g_h1 [(size_t)MAXN * F1];     // x @ W1 (fp32, gathered in layer 1)
__device__ uint4 g_o1h[(size_t)MAXN * 32];     // out1 bf16 hi
__device__ uint4 g_o1l[(size_t)MAXN * 32];     // out1 bf16 lo
__device__ float g_h2 [(size_t)MAXN * OUTC];
__device__ float g_as1[MAXN * HH];
__device__ float g_ad1[MAXN * HH];
__device__ float g_as2[MAXN];
__device__ float g_ad2[MAXN];

// W1^T bf16 hi/lo, FRAGMENT-CONTIGUOUS layout:
// fragment f(ch, n8, k16) = 64 uint32 (256B); lane reads uint2 at frag+lane*8.
__device__ uint32_t g_W1f_hi[256 * 128];
__device__ uint32_t g_W1f_lo[256 * 128];
// W2^T bf16 hi/lo, [n=40][k2=128]
__device__ uint32_t g_W2t_hi[40 * 128];
__device__ uint32_t g_W2t_lo[40 * 128];

// CSR by destination (g_deg zero-initialized at module load; gat2 re-zeroes it
// after last use each replay, so no zero_deg kernel is needed)
__device__ int g_deg   [MAXN];
__device__ int g_rowptr[MAXN];
__device__ int g_cursor[MAXN];
__device__ int g_csr   [MAXET];
__device__ int g_btot  [128];
__device__ int g_boff  [128];

// ---------------------------------------------------------------------------
// Helpers
// ---------------------------------------------------------------------------
__device__ __forceinline__ void split2(float a, float b, uint32_t& hi, uint32_t& lo) {
    __nv_bfloat16 ha = __float2bfloat16(a);
    __nv_bfloat16 hb = __float2bfloat16(b);
    __nv_bfloat16 la = __float2bfloat16(a - __bfloat162float(ha));
    __nv_bfloat16 lb = __float2bfloat16(b - __bfloat162float(hb));
    __nv_bfloat162 h = __halves2bfloat162(ha, hb);
    __nv_bfloat162 l = __halves2bfloat162(la, lb);
    hi = *reinterpret_cast<uint32_t*>(&h);
    lo = *reinterpret_cast<uint32_t*>(&l);
}

__device__ __forceinline__ void ldsm4(uint32_t* r, uint32_t addr) {
    asm volatile("ldmatrix.sync.aligned.m8n8.x4.shared.b16 {%0,%1,%2,%3}, [%4];"
        : "=r"(r[0]), "=r"(r[1]), "=r"(r[2]), "=r"(r[3]) : "r"(addr));
}

__device__ __forceinline__ void mma16816(float* c, const uint32_t* a, const uint32_t* b) {
    asm volatile(
        "mma.sync.aligned.m16n8k16.row.col.f32.bf16.bf16.f32 "
        "{%0,%1,%2,%3}, {%4,%5,%6,%7}, {%8,%9}, {%0,%1,%2,%3};\n"
        : "+f"(c[0]), "+f"(c[1]), "+f"(c[2]), "+f"(c[3])
        : "r"(a[0]), "r"(a[1]), "r"(a[2]), "r"(a[3]), "r"(b[0]), "r"(b[1]));
}

// ---------------------------------------------------------------------------
// Weight prep: W1 [k=256][n=256] -> fragment-contiguous bf16 hi/lo
// ---------------------------------------------------------------------------
__global__ void prep_W(const float* __restrict__ W) {
    int t = blockIdx.x * blockDim.x + threadIdx.x;
    if (t >= 256 * 128) return;
    int n = t >> 7, j = t & 127;            // n = output col, j = k2 index
    uint32_t h, l;
    split2(W[(size_t)(2 * j) * 256 + n], W[(size_t)(2 * j + 1) * 256 + n], h, l);
    int ch = n >> 7, nh = n & 127;
    int n8 = nh >> 3, ncol = nh & 7;
    int k16 = j >> 3, kp = (j >> 2) & 1, bt = j & 3;
    int lane = ncol * 4 + bt;
    int idx = (((ch * 16 + n8) * 16 + k16) * 32 + lane) * 2 + kp;
    g_W1f_hi[idx] = h;
    g_W1f_lo[idx] = l;
}

__global__ void prep_W2(const float* __restrict__ W2) {  // W2 [256][40]
    int t = blockIdx.x * blockDim.x + threadIdx.x;
    if (t >= 40 * 128) return;
    int n = t >> 7, k2 = t & 127, k = k2 * 2;
    uint32_t h, l;
    split2(W2[(size_t)k * OUTC + n], W2[(size_t)(k + 1) * OUTC + n], h, l);
    g_W2t_hi[n * 128 + k2] = h;
    g_W2t_lo[n * 128 + k2] = l;
}

// ---------------------------------------------------------------------------
// GEMM1 (tensor cores): g_h1[M,256] = x[M,256] @ W1[256,256], bf16 split.
// A through smem; B fragments direct from global, fragment-contiguous.
// Fused a1 projection in the epilogue.
// ---------------------------------------------------------------------------
__global__ __launch_bounds__(256, 2)
void mma_gemm1(const float* __restrict__ A,
               const float* __restrict__ att_s, const float* __restrict__ att_d, int M) {
    __shared__ uint4 As_hi[512], As_lo[512];   // 128 rows x 4 chunks (16B)

    int tid = threadIdx.x;
    int lane = tid & 31, w = tid >> 5;
    int warp_m = w & 3, warp_n = w >> 2;
    int row0 = blockIdx.y * 128;
    int col0 = blockIdx.x * 128;

    uint32_t as_hi_b = (uint32_t)__cvta_generic_to_shared(As_hi);
    uint32_t as_lo_b = (uint32_t)__cvta_generic_to_shared(As_lo);

    const uint2* Wfh = (const uint2*)g_W1f_hi;
    const uint2* Wfl = (const uint2*)g_W1f_lo;
    int half16 = blockIdx.x * 16;

    float C[2][8][4];
#pragma unroll
    for (int mt = 0; mt < 2; mt++)
#pragma unroll
        for (int nt = 0; nt < 8; nt++)
#pragma unroll
            for (int i = 0; i < 4; i++) C[mt][nt][i] = 0.f;

    int lr = lane & 15, lh = lane >> 4;

    for (int kc = 0; kc < 8; kc++) {
        int k0 = kc * 32;
        __syncthreads();
#pragma unroll
        for (int j = 0; j < 2; j++) {
            int cid = j * 256 + tid;
            int row = cid >> 2;
            int ch  = cid & 3;
            int gr = row0 + row;
            float4 f0 = make_float4(0.f, 0.f, 0.f, 0.f), f1 = f0;
            if (gr < M) {
                const float4* p = (const float4*)(A + (size_t)gr * 256 + k0 + ch * 8);
                f0 = p[0]; f1 = p[1];
            }
            uint32_t h[4], l[4];
            split2(f0.x, f0.y, h[0], l[0]);
            split2(f0.z, f0.w, h[1], l[1]);
            split2(f1.x, f1.y, h[2], l[2]);
            split2(f1.z, f1.w, h[3], l[3]);
            int off = row * 4 + (ch ^ (row & 3));
            As_hi[off] = make_uint4(h[0], h[1], h[2], h[3]);
            As_lo[off] = make_uint4(l[0], l[1], l[2], l[3]);
        }
        __syncthreads();

#pragma unroll
        for (int ks = 0; ks < 2; ks++) {
            int kk2 = ks * 2;
            int blk = kc * 2 + ks;
            uint32_t a_hi[2][4], a_lo[2][4];
#pragma unroll
            for (int mt = 0; mt < 2; mt++) {
                int r = warp_m * 32 + mt * 16 + lr;
                int c = kk2 + lh;
                uint32_t bo = (uint32_t)(r * 4 + (c ^ (r & 3))) * 16;
                ldsm4(a_hi[mt], as_hi_b + bo);
                ldsm4(a_lo[mt], as_lo_b + bo);
            }
#pragma unroll
            for (int ng = 0; ng < 4; ng++) {
                int n8a = warp_n * 8 + ng * 2;
                size_t f0 = ((size_t)(half16 + n8a) * 16 + blk) * 32 + lane;
                size_t f1 = f0 + 16 * 32;
                uint2 bh0 = Wfh[f0], bh1 = Wfh[f1];
                uint2 bl0 = Wfl[f0], bl1 = Wfl[f1];
                uint32_t rbh0[2] = {bh0.x, bh0.y}, rbh1[2] = {bh1.x, bh1.y};
                uint32_t rbl0[2] = {bl0.x, bl0.y}, rbl1[2] = {bl1.x, bl1.y};
                int nt0 = ng * 2, nt1 = ng * 2 + 1;
#pragma unroll
                for (int mt = 0; mt < 2; mt++) {
                    mma16816(C[mt][nt0], a_hi[mt], rbh0);
                    mma16816(C[mt][nt0], a_hi[mt], rbl0);
                    mma16816(C[mt][nt0], a_lo[mt], rbh0);
                    mma16816(C[mt][nt1], a_hi[mt], rbh1);
                    mma16816(C[mt][nt1], a_hi[mt], rbl1);
                    mma16816(C[mt][nt1], a_lo[mt], rbh1);
                }
            }
        }
    }

    // ---- epilogue: store h1 + fused a1 projection ----
    int qr = lane >> 2, qc = lane & 3;
#pragma unroll
    for (int mt = 0; mt < 2; mt++) {
        int r = row0 + warp_m * 32 + mt * 16 + qr;
        float ps[2][2] = {{0.f, 0.f}, {0.f, 0.f}};
        float pd[2][2] = {{0.f, 0.f}, {0.f, 0.f}};
#pragma unroll
        for (int nt = 0; nt < 8; nt++) {
            int cg = col0 + warp_n * 64 + nt * 8 + qc * 2;
            int hs = nt >> 2;
            float s0 = __ldg(att_s + cg), s1 = __ldg(att_s + cg + 1);
            float e0 = __ldg(att_d + cg), e1 = __ldg(att_d + cg + 1);
            ps[hs][0] += C[mt][nt][0] * s0 + C[mt][nt][1] * s1;
            pd[hs][0] += C[mt][nt][0] * e0 + C[mt][nt][1] * e1;
            ps[hs][1] += C[mt][nt][2] * s0 + C[mt][nt][3] * s1;
            pd[hs][1] += C[mt][nt][2] * e0 + C[mt][nt][3] * e1;
            if (r < M)
                *(float2*)(g_h1 + (size_t)r * 256 + cg) = make_float2(C[mt][nt][0], C[mt][nt][1]);
            if (r + 8 < M)
                *(float2*)(g_h1 + (size_t)(r + 8) * 256 + cg) = make_float2(C[mt][nt][2], C[mt][nt][3]);
        }
#pragma unroll
        for (int o = 1; o <= 2; o <<= 1) {
#pragma unroll
            for (int hs = 0; hs < 2; hs++)
#pragma unroll
                for (int ri = 0; ri < 2; ri++) {
                    ps[hs][ri] += __shfl_xor_sync(0xffffffffu, ps[hs][ri], o);
                    pd[hs][ri] += __shfl_xor_sync(0xffffffffu, pd[hs][ri], o);
                }
        }
        if (qc == 0) {
            int headb = (col0 >> 5) + warp_n * 2;
            if (r < M) {
                g_as1[r * 8 + headb]     = ps[0][0];
                g_as1[r * 8 + headb + 1] = ps[1][0];
                g_ad1[r * 8 + headb]     = pd[0][0];
                g_ad1[r * 8 + headb + 1] = pd[1][0];
            }
            if (r + 8 < M) {
                g_as1[(r + 8) * 8 + headb]     = ps[0][1];
                g_as1[(r + 8) * 8 + headb + 1] = ps[1][1];
                g_ad1[(r + 8) * 8 + headb]     = pd[0][1];
                g_ad1[(r + 8) * 8 + headb + 1] = pd[1][1];
            }
        }
    }
}

// ---------------------------------------------------------------------------
// CSR construction (no zero_deg: deg is re-zeroed by gat2 each replay)
// ---------------------------------------------------------------------------
__global__ void count_deg(const int* __restrict__ dst, int E, int ET) {
    int e = blockIdx.x * blockDim.x + threadIdx.x;
    if (e >= ET) return;
    int d = (e < E) ? dst[e] : (e - E);
    atomicAdd(&g_deg[d], 1);
}

__global__ void scan_local(int M) {
    __shared__ int wsum[32];
    int b = blockIdx.x, tid = threadIdx.x, lane = tid & 31, w = tid >> 5;
    int i = b * 1024 + tid;
    int v = (i < M) ? g_deg[i] : 0;
    int x = v;
#pragma unroll
    for (int o = 1; o < 32; o <<= 1) {
        int y = __shfl_up_sync(0xffffffffu, x, o);
        if (lane >= o) x += y;
    }
    if (lane == 31) wsum[w] = x;
    __syncthreads();
    if (w == 0) {
        int s = wsum[lane];
#pragma unroll
        for (int o = 1; o < 32; o <<= 1) {
            int y = __shfl_up_sync(0xffffffffu, s, o);
            if (lane >= o) s += y;
        }
        wsum[lane] = s;
    }
    __syncthreads();
    int excl = (w > 0 ? wsum[w - 1] : 0) + x - v;
    if (i < M) g_rowptr[i] = excl;
    if (tid == 1023) g_btot[b] = wsum[31];
}

__global__ void scan_tops(int nb) {
    if (threadIdx.x == 0) {
        int s = 0;
        for (int j = 0; j < nb; j++) { g_boff[j] = s; s += g_btot[j]; }
    }
}

__global__ void add_off(int M) {
    int b = blockIdx.x;
    int i = b * 1024 + threadIdx.x;
    if (i < M) {
        int v = g_rowptr[i] + g_boff[b];
        g_rowptr[i] = v;
        g_cursor[i] = v;
    }
}

__global__ void scatter_csr(const int* __restrict__ src, const int* __restrict__ dst,
                            int E, int ET) {
    int e = blockIdx.x * blockDim.x + threadIdx.x;
    if (e >= ET) return;
    int s, d;
    if (e < E) { s = src[e]; d = dst[e]; } else { s = e - E; d = s; }
    int pos = atomicAdd(&g_cursor[d], 1);
    g_csr[pos] = s;
}

// ---------------------------------------------------------------------------
// Layer-1 fused: warp per dst node, channels in registers.
// No-max softmax (logits bounded ~8 << 88): plain exp, per-lane deferred
// denominator, ZERO per-chunk reductions, no acc rescaling.
// ---------------------------------------------------------------------------
__global__ __launch_bounds__(256)
void gat1_fused(const float* __restrict__ b1, int M) {
    __shared__ float s_w[8 * 256];
    int lane = threadIdx.x & 31, w = threadIdx.x >> 5;
    int node = blockIdx.x * 8 + w;
    if (node >= M) return;
    float* sw = s_w + w * 256;
    int hl = lane >> 2;

    float4 d0 = *(const float4*)(g_ad1 + (size_t)node * HH);
    float4 d1 = *(const float4*)(g_ad1 + (size_t)node * HH + 4);
    float adst[8] = {d0.x, d0.y, d0.z, d0.w, d1.x, d1.y, d1.z, d1.w};

    int start = g_rowptr[node];
    int deg   = g_deg[node];

    float den[8], acc[8];
#pragma unroll
    for (int h = 0; h < 8; h++) { den[h] = 0.f; acc[h] = 0.f; }

    for (int base = 0; base < deg; base += 32) {
        int nE = min(32, deg - base);
        int s = 0;
        float ex[8];
        if (lane < nE) {
            s = g_csr[start + base + lane];
            float4 a0 = *(const float4*)(g_as1 + (size_t)s * HH);
            float4 a1 = *(const float4*)(g_as1 + (size_t)s * HH + 4);
            float as[8] = {a0.x, a0.y, a0.z, a0.w, a1.x, a1.y, a1.z, a1.w};
#pragma unroll
            for (int h = 0; h < 8; h++) {
                float v = as[h] + adst[h];
                v = v > 0.f ? v : 0.2f * v;
                ex[h] = __expf(v);
            }
        } else {
#pragma unroll
            for (int h = 0; h < 8; h++) ex[h] = 0.f;
        }
#pragma unroll
        for (int h = 0; h < 8; h++) {
            den[h] += ex[h];
            sw[h * 32 + ((lane + h * 4) & 31)] = ex[h];
        }
        __syncwarp();

        const float* hbase = g_h1 + (size_t)lane * 8;
        int e = 0;
        for (; e + 4 <= nE; e += 4) {
            int s0 = __shfl_sync(0xffffffffu, s, e);
            int s1 = __shfl_sync(0xffffffffu, s, e + 1);
            int s2 = __shfl_sync(0xffffffffu, s, e + 2);
            int s3 = __shfl_sync(0xffffffffu, s, e + 3);
            float w0 = sw[hl * 32 + ((e     + hl * 4) & 31)];
            float w1 = sw[hl * 32 + ((e + 1 + hl * 4) & 31)];
            float w2 = sw[hl * 32 + ((e + 2 + hl * 4) & 31)];
            float w3 = sw[hl * 32 + ((e + 3 + hl * 4) & 31)];
            const float4* p0 = (const float4*)(hbase + (size_t)s0 * 256);
            const float4* p1 = (const float4*)(hbase + (size_t)s1 * 256);
            const float4* p2 = (const float4*)(hbase + (size_t)s2 * 256);
            const float4* p3 = (const float4*)(hbase + (size_t)s3 * 256);
            float4 u0 = p0[0], u1 = p0[1];
            float4 v0 = p1[0], v1 = p1[1];
            float4 x0 = p2[0], x1 = p2[1];
            float4 y0 = p3[0], y1 = p3[1];
            acc[0] += u0.x * w0 + v0.x * w1 + x0.x * w2 + y0.x * w3;
            acc[1] += u0.y * w0 + v0.y * w1 + x0.y * w2 + y0.y * w3;
            acc[2] += u0.z * w0 + v0.z * w1 + x0.z * w2 + y0.z * w3;
            acc[3] += u0.w * w0 + v0.w * w1 + x0.w * w2 + y0.w * w3;
            acc[4] += u1.x * w0 + v1.x * w1 + x1.x * w2 + y1.x * w3;
            acc[5] += u1.y * w0 + v1.y * w1 + x1.y * w2 + y1.y * w3;
            acc[6] += u1.z * w0 + v1.z * w1 + x1.z * w2 + y1.z * w3;
            acc[7] += u1.w * w0 + v1.w * w1 + x1.w * w2 + y1.w * w3;
        }
        for (; e < nE; e++) {
            int s0 = __shfl_sync(0xffffffffu, s, e);
            float w0 = sw[hl * 32 + ((e + hl * 4) & 31)];
            const float4* p0 = (const float4*)(hbase + (size_t)s0 * 256);
            float4 u0 = p0[0], u1 = p0[1];
            acc[0] += u0.x * w0; acc[1] += u0.y * w0;
            acc[2] += u0.z * w0; acc[3] += u0.w * w0;
            acc[4] += u1.x * w0; acc[5] += u1.y * w0;
            acc[6] += u1.z * w0; acc[7] += u1.w * w0;
        }
        __syncwarp();
    }

    // single deferred denominator reduction per node
#pragma unroll
    for (int h = 0; h < 8; h++) {
        float d = den[h];
#pragma unroll
        for (int o = 16; o > 0; o >>= 1)
            d += __shfl_xor_sync(0xffffffffu, d, o);
        den[h] = d;
    }
    float dsel = den[0];
#pragma unroll
    for (int h = 1; h < 8; h++) if (hl == h) dsel = den[h];
    float inv = 1.f / (dsel + 1e-16f);
    uint32_t oh[4], ol[4];
#pragma unroll
    for (int i = 0; i < 4; i++) {
        float o0 = acc[2 * i]     * inv + __ldg(b1 + lane * 8 + 2 * i);
        float o1 = acc[2 * i + 1] * inv + __ldg(b1 + lane * 8 + 2 * i + 1);
        o0 = o0 > 0.f ? o0 : expm1f(o0);
        o1 = o1 > 0.f ? o1 : expm1f(o1);
        split2(o0, o1, oh[i], ol[i]);
    }
    g_o1h[(size_t)node * 32 + lane] = make_uint4(oh[0], oh[1], oh[2], oh[3]);
    g_o1l[(size_t)node * 32 + lane] = make_uint4(ol[0], ol[1], ol[2], ol[3]);
}

// ---------------------------------------------------------------------------
// GEMM2 (tensor cores, register-only) + fused a2 projection
// ---------------------------------------------------------------------------
__global__ __launch_bounds__(256)
void mma_gemm2(const float* __restrict__ att_s, const float* __restrict__ att_d, int M) {
    int lane = threadIdx.x & 31, w = threadIdx.x >> 5;
    int g = lane >> 2, t = lane & 3;
    int rA  = blockIdx.x * 128 + w * 16 + g;
    int rA8 = rA + 8;
    int rAc  = min(rA,  M - 1);
    int rA8c = min(rA8, M - 1);

    const uint32_t* Ah = (const uint32_t*)g_o1h;
    const uint32_t* Al = (const uint32_t*)g_o1l;
    const uint32_t* p0h = Ah + (size_t)rAc  * 128 + t;
    const uint32_t* p1h = Ah + (size_t)rA8c * 128 + t;
    const uint32_t* p0l = Al + (size_t)rAc  * 128 + t;
    const uint32_t* p1l = Al + (size_t)rA8c * 128 + t;

    float C[5][4];
#pragma unroll
    for (int nt = 0; nt < 5; nt++)
#pragma unroll
        for (int i = 0; i < 4; i++) C[nt][i] = 0.f;

#pragma unroll
    for (int kk2 = 0; kk2 < 128; kk2 += 8) {
        uint32_t ah[4], al[4];
        ah[0] = p0h[kk2];     ah[1] = p1h[kk2];
        ah[2] = p0h[kk2 + 4]; ah[3] = p1h[kk2 + 4];
        al[0] = p0l[kk2];     al[1] = p1l[kk2];
        al[2] = p0l[kk2 + 4]; al[3] = p1l[kk2 + 4];
#pragma unroll
        for (int nt = 0; nt < 5; nt++) {
            int nb = (nt * 8 + g) * 128 + kk2 + t;
            uint32_t bh[2] = { g_W2t_hi[nb], g_W2t_hi[nb + 4] };
            uint32_t bl[2] = { g_W2t_lo[nb], g_W2t_lo[nb + 4] };
            mma16816(C[nt], ah, bh);
            mma16816(C[nt], ah, bl);
            mma16816(C[nt], al, bh);
        }
    }

    float ps0 = 0.f, pd0 = 0.f, ps1 = 0.f, pd1 = 0.f;
#pragma unroll
    for (int nt = 0; nt < 5; nt++) {
        int col = nt * 8 + t * 2;
        float s0 = __ldg(att_s + col), s1 = __ldg(att_s + col + 1);
        float e0 = __ldg(att_d + col), e1 = __ldg(att_d + col + 1);
        ps0 += C[nt][0] * s0 + C[nt][1] * s1;
        pd0 += C[nt][0] * e0 + C[nt][1] * e1;
        ps1 += C[nt][2] * s0 + C[nt][3] * s1;
        pd1 += C[nt][2] * e0 + C[nt][3] * e1;
        if (rA < M)
            *(float2*)(g_h2 + (size_t)rA * OUTC + col) = make_float2(C[nt][0], C[nt][1]);
        if (rA8 < M)
            *(float2*)(g_h2 + (size_t)rA8 * OUTC + col) = make_float2(C[nt][2], C[nt][3]);
    }
#pragma unroll
    for (int o = 1; o <= 2; o <<= 1) {
        ps0 += __shfl_xor_sync(0xffffffffu, ps0, o);
        pd0 += __shfl_xor_sync(0xffffffffu, pd0, o);
        ps1 += __shfl_xor_sync(0xffffffffu, ps1, o);
        pd1 += __shfl_xor_sync(0xffffffffu, pd1, o);
    }
    if (t == 0) {
        if (rA < M)  { g_as2[rA]  = ps0; g_ad2[rA]  = pd0; }
        if (rA8 < M) { g_as2[rA8] = ps1; g_ad2[rA8] = pd1; }
    }
}

// ---------------------------------------------------------------------------
// Layer-2 fused (no-max softmax, deferred denominator). Warp per dst node.
// Also re-zeroes g_deg after last use (replaces zero_deg kernel).
// ---------------------------------------------------------------------------
__global__ __launch_bounds__(256)
void gat2_fused(float* __restrict__ out, const float* __restrict__ b2, int M) {
    int gw = (blockIdx.x * blockDim.x + threadIdx.x) >> 5;
    if (gw >= M) return;
    int lane = threadIdx.x & 31;

    int start = g_rowptr[gw];
    int deg   = g_deg[gw];
    if (lane == 0) g_deg[gw] = 0;            // reset for next replay
    float ad = g_ad2[gw];
    float den_l = 0.f, acc0 = 0.f, acc1 = 0.f;

    for (int base = 0; base < deg; base += 32) {
        int nE = min(32, deg - base);
        int s = 0;
        float ex = 0.f;
        if (lane < nE) {
            s = g_csr[start + base + lane];
            float t = g_as2[s] + ad;
            t = t > 0.f ? t : 0.2f * t;
            ex = __expf(t);
        }
        den_l += ex;
        for (int e = 0; e < nE; e++) {
            float a  = __shfl_sync(0xffffffffu, ex, e);
            int   se = __shfl_sync(0xffffffffu, s, e);
            const float* r = g_h2 + (size_t)se * OUTC;
            acc0 += r[lane] * a;
            if (lane < 8) acc1 += r[32 + lane] * a;
        }
    }
    float den = den_l;
#pragma unroll
    for (int o = 16; o > 0; o >>= 1)
        den += __shfl_xor_sync(0xffffffffu, den, o);
    float inv = 1.f / (den + 1e-16f);
    out[(size_t)gw * OUTC + lane] = acc0 * inv + __ldg(b2 + lane);
    if (lane < 8)
        out[(size_t)gw * OUTC + 32 + lane] = acc1 * inv + __ldg(b2 + 32 + lane);
}

// ---------------------------------------------------------------------------
// Launcher: fork-join, with mma_gemm1 as the 4th kernel CALL (the slot ncu
// profiles) to verify the fragment-B roofline.
// ---------------------------------------------------------------------------
extern "C" void kernel_launch(void* const* d_in, const int* in_sizes, int n_in,
                              void* d_out, int out_size) {
    const float* x      = (const float*)d_in[0];
    const int*   ei     = (const int*)  d_in[1];
    const float* W1     = (const float*)d_in[2];
    const float* att_s1 = (const float*)d_in[3];
    const float* att_d1 = (const float*)d_in[4];
    const float* b1     = (const float*)d_in[5];
    const float* W2     = (const float*)d_in[6];
    const float* att_s2 = (const float*)d_in[7];
    const float* att_d2 = (const float*)d_in[8];
    const float* b2     = (const float*)d_in[9];
    float* out = (float*)d_out;

    int M  = in_sizes[0] / F1;
    int E  = in_sizes[1] / 2;
    int ET = E + M;
    int eb = (ET + 255) / 256;
    int nb = (M + 1023) / 1024;

    static cudaStream_t s2 = nullptr;
    static cudaEvent_t ev_fork = nullptr, ev_join = nullptr;
    if (s2 == nullptr) {
        cudaStreamCreateWithFlags(&s2, cudaStreamNonBlocking);
        cudaEventCreateWithFlags(&ev_fork, cudaEventDisableTiming);
        cudaEventCreateWithFlags(&ev_join, cudaEventDisableTiming);
    }

    // fork
    cudaEventRecord(ev_fork, 0);
    cudaStreamWaitEvent(s2, ev_fork, 0);

    prep_W<<<128, 256>>>(W1);                                            // call 1 (s0)
    count_deg<<<eb, 256, 0, s2>>>(ei + E, E, ET);                        // call 2 (s2)
    scan_local<<<nb, 1024, 0, s2>>>(M);                                  // call 3 (s2)
    mma_gemm1<<<dim3(2, (M + 127) / 128), 256>>>(x, att_s1, att_d1, M);  // call 4 (s0) <- profiled
    scan_tops<<<1, 32, 0, s2>>>(nb);                                     // call 5 (s2)
    add_off<<<nb, 1024, 0, s2>>>(M);                                     // call 6 (s2)
    scatter_csr<<<eb, 256, 0, s2>>>(ei, ei + E, E, ET);                  // call 7 (s2)
    prep_W2<<<20, 256, 0, s2>>>(W2);                                     // call 8 (s2)
    cudaEventRecord(ev_join, s2);

    // join
    cudaStreamWaitEvent(0, ev_join, 0);

    gat1_fused<<<(M + 7) / 8, 256>>>(b1, M);                             // call 9
    mma_gemm2<<<(M + 127) / 128, 256>>>(att_s2, att_d2, M);              // call 10
    gat2_fused<<<(M * 32 + 255) / 256, 256>>>(out, b2, M);               // call 11
}

// round 13
// speedup vs baseline: 1.0050x; 1.0050x over previous
#include <cuda_runtime.h>
#include <cuda_bf16.h>
#include <math.h>
#include <stdint.h>

// ---------------------------------------------------------------------------
// Problem constants
// ---------------------------------------------------------------------------
#define MAXN 100000
#define MAXE 800000
#define MAXET (MAXE + MAXN)
#define F1 256
#define HH 8
#define OUTC 40

// ---------------------------------------------------------------------------
// Scratch
// ---------------------------------------------------------------------------
__device__ float g_h1 [(size_t)MAXN * F1];     // x @ W1 (fp32, gathered in layer 1)
__device__ uint4 g_o1h[(size_t)MAXN * 32];     // out1 bf16 hi
__device__ uint4 g_o1l[(size_t)MAXN * 32];     // out1 bf16 lo
__device__ float g_h2 [(size_t)MAXN * OUTC];
__device__ float g_as1[MAXN * HH];
__device__ float g_ad1[MAXN * HH];
__device__ float g_as2[MAXN];
__device__ float g_ad2[MAXN];

// W1^T bf16 hi/lo, FRAGMENT-CONTIGUOUS layout (verified: gemm1 200->144us):
// fragment f(ch, n8, k16) = 64 uint32 (256B); lane reads uint2 at frag+lane*8.
__device__ uint32_t g_W1f_hi[256 * 128];
__device__ uint32_t g_W1f_lo[256 * 128];
// W2^T bf16 hi/lo, [n=40][k2=128]
__device__ uint32_t g_W2t_hi[40 * 128];
__device__ uint32_t g_W2t_lo[40 * 128];

// CSR by destination (g_deg zero-initialized at module load; gat2 re-zeroes it
// after last use each replay, so no zero_deg kernel is needed)
__device__ int g_deg   [MAXN];
__device__ int g_rowptr[MAXN];
__device__ int g_cursor[MAXN];
__device__ int g_csr   [MAXET];
__device__ int g_btot  [128];
__device__ int g_boff  [128];

// ---------------------------------------------------------------------------
// Helpers
// ---------------------------------------------------------------------------
__device__ __forceinline__ void split2(float a, float b, uint32_t& hi, uint32_t& lo) {
    __nv_bfloat16 ha = __float2bfloat16(a);
    __nv_bfloat16 hb = __float2bfloat16(b);
    __nv_bfloat16 la = __float2bfloat16(a - __bfloat162float(ha));
    __nv_bfloat16 lb = __float2bfloat16(b - __bfloat162float(hb));
    __nv_bfloat162 h = __halves2bfloat162(ha, hb);
    __nv_bfloat162 l = __halves2bfloat162(la, lb);
    hi = *reinterpret_cast<uint32_t*>(&h);
    lo = *reinterpret_cast<uint32_t*>(&l);
}

__device__ __forceinline__ void ldsm4(uint32_t* r, uint32_t addr) {
    asm volatile("ldmatrix.sync.aligned.m8n8.x4.shared.b16 {%0,%1,%2,%3}, [%4];"
        : "=r"(r[0]), "=r"(r[1]), "=r"(r[2]), "=r"(r[3]) : "r"(addr));
}

__device__ __forceinline__ void mma16816(float* c, const uint32_t* a, const uint32_t* b) {
    asm volatile(
        "mma.sync.aligned.m16n8k16.row.col.f32.bf16.bf16.f32 "
        "{%0,%1,%2,%3}, {%4,%5,%6,%7}, {%8,%9}, {%0,%1,%2,%3};\n"
        : "+f"(c[0]), "+f"(c[1]), "+f"(c[2]), "+f"(c[3])
        : "r"(a[0]), "r"(a[1]), "r"(a[2]), "r"(a[3]), "r"(b[0]), "r"(b[1]));
}

// ---------------------------------------------------------------------------
// Weight prep: W1 [k=256][n=256] -> fragment-contiguous bf16 hi/lo
// ---------------------------------------------------------------------------
__global__ void prep_W(const float* __restrict__ W) {
    int t = blockIdx.x * blockDim.x + threadIdx.x;
    if (t >= 256 * 128) return;
    int n = t >> 7, j = t & 127;            // n = output col, j = k2 index
    uint32_t h, l;
    split2(W[(size_t)(2 * j) * 256 + n], W[(size_t)(2 * j + 1) * 256 + n], h, l);
    int ch = n >> 7, nh = n & 127;
    int n8 = nh >> 3, ncol = nh & 7;
    int k16 = j >> 3, kp = (j >> 2) & 1, bt = j & 3;
    int lane = ncol * 4 + bt;
    int idx = (((ch * 16 + n8) * 16 + k16) * 32 + lane) * 2 + kp;
    g_W1f_hi[idx] = h;
    g_W1f_lo[idx] = l;
}

__global__ void prep_W2(const float* __restrict__ W2) {  // W2 [256][40]
    int t = blockIdx.x * blockDim.x + threadIdx.x;
    if (t >= 40 * 128) return;
    int n = t >> 7, k2 = t & 127, k = k2 * 2;
    uint32_t h, l;
    split2(W2[(size_t)k * OUTC + n], W2[(size_t)(k + 1) * OUTC + n], h, l);
    g_W2t_hi[n * 128 + k2] = h;
    g_W2t_lo[n * 128 + k2] = l;
}

// ---------------------------------------------------------------------------
// GEMM1 (tensor cores): g_h1[M,256] = x[M,256] @ W1[256,256], bf16 split.
// A through smem; B fragments direct from global, fragment-contiguous.
// Fused a1 projection in the epilogue.  (ncu-verified 144us)
// ---------------------------------------------------------------------------
__global__ __launch_bounds__(256, 2)
void mma_gemm1(const float* __restrict__ A,
               const float* __restrict__ att_s, const float* __restrict__ att_d, int M) {
    __shared__ uint4 As_hi[512], As_lo[512];   // 128 rows x 4 chunks (16B)

    int tid = threadIdx.x;
    int lane = tid & 31, w = tid >> 5;
    int warp_m = w & 3, warp_n = w >> 2;
    int row0 = blockIdx.y * 128;
    int col0 = blockIdx.x * 128;

    uint32_t as_hi_b = (uint32_t)__cvta_generic_to_shared(As_hi);
    uint32_t as_lo_b = (uint32_t)__cvta_generic_to_shared(As_lo);

    const uint2* Wfh = (const uint2*)g_W1f_hi;
    const uint2* Wfl = (const uint2*)g_W1f_lo;
    int half16 = blockIdx.x * 16;

    float C[2][8][4];
#pragma unroll
    for (int mt = 0; mt < 2; mt++)
#pragma unroll
        for (int nt = 0; nt < 8; nt++)
#pragma unroll
            for (int i = 0; i < 4; i++) C[mt][nt][i] = 0.f;

    int lr = lane & 15, lh = lane >> 4;

    for (int kc = 0; kc < 8; kc++) {
        int k0 = kc * 32;
        __syncthreads();
#pragma unroll
        for (int j = 0; j < 2; j++) {
            int cid = j * 256 + tid;
            int row = cid >> 2;
            int ch  = cid & 3;
            int gr = row0 + row;
            float4 f0 = make_float4(0.f, 0.f, 0.f, 0.f), f1 = f0;
            if (gr < M) {
                const float4* p = (const float4*)(A + (size_t)gr * 256 + k0 + ch * 8);
                f0 = p[0]; f1 = p[1];
            }
            uint32_t h[4], l[4];
            split2(f0.x, f0.y, h[0], l[0]);
            split2(f0.z, f0.w, h[1], l[1]);
            split2(f1.x, f1.y, h[2], l[2]);
            split2(f1.z, f1.w, h[3], l[3]);
            int off = row * 4 + (ch ^ (row & 3));
            As_hi[off] = make_uint4(h[0], h[1], h[2], h[3]);
            As_lo[off] = make_uint4(l[0], l[1], l[2], l[3]);
        }
        __syncthreads();

#pragma unroll
        for (int ks = 0; ks < 2; ks++) {
            int kk2 = ks * 2;
            int blk = kc * 2 + ks;
            uint32_t a_hi[2][4], a_lo[2][4];
#pragma unroll
            for (int mt = 0; mt < 2; mt++) {
                int r = warp_m * 32 + mt * 16 + lr;
                int c = kk2 + lh;
                uint32_t bo = (uint32_t)(r * 4 + (c ^ (r & 3))) * 16;
                ldsm4(a_hi[mt], as_hi_b + bo);
                ldsm4(a_lo[mt], as_lo_b + bo);
            }
#pragma unroll
            for (int ng = 0; ng < 4; ng++) {
                int n8a = warp_n * 8 + ng * 2;
                size_t f0 = ((size_t)(half16 + n8a) * 16 + blk) * 32 + lane;
                size_t f1 = f0 + 16 * 32;
                uint2 bh0 = Wfh[f0], bh1 = Wfh[f1];
                uint2 bl0 = Wfl[f0], bl1 = Wfl[f1];
                uint32_t rbh0[2] = {bh0.x, bh0.y}, rbh1[2] = {bh1.x, bh1.y};
                uint32_t rbl0[2] = {bl0.x, bl0.y}, rbl1[2] = {bl1.x, bl1.y};
                int nt0 = ng * 2, nt1 = ng * 2 + 1;
#pragma unroll
                for (int mt = 0; mt < 2; mt++) {
                    mma16816(C[mt][nt0], a_hi[mt], rbh0);
                    mma16816(C[mt][nt0], a_hi[mt], rbl0);
                    mma16816(C[mt][nt0], a_lo[mt], rbh0);
                    mma16816(C[mt][nt1], a_hi[mt], rbh1);
                    mma16816(C[mt][nt1], a_hi[mt], rbl1);
                    mma16816(C[mt][nt1], a_lo[mt], rbh1);
                }
            }
        }
    }

    // ---- epilogue: store h1 + fused a1 projection ----
    int qr = lane >> 2, qc = lane & 3;
#pragma unroll
    for (int mt = 0; mt < 2; mt++) {
        int r = row0 + warp_m * 32 + mt * 16 + qr;
        float ps[2][2] = {{0.f, 0.f}, {0.f, 0.f}};
        float pd[2][2] = {{0.f, 0.f}, {0.f, 0.f}};
#pragma unroll
        for (int nt = 0; nt < 8; nt++) {
            int cg = col0 + warp_n * 64 + nt * 8 + qc * 2;
            int hs = nt >> 2;
            float s0 = __ldg(att_s + cg), s1 = __ldg(att_s + cg + 1);
            float e0 = __ldg(att_d + cg), e1 = __ldg(att_d + cg + 1);
            ps[hs][0] += C[mt][nt][0] * s0 + C[mt][nt][1] * s1;
            pd[hs][0] += C[mt][nt][0] * e0 + C[mt][nt][1] * e1;
            ps[hs][1] += C[mt][nt][2] * s0 + C[mt][nt][3] * s1;
            pd[hs][1] += C[mt][nt][2] * e0 + C[mt][nt][3] * e1;
            if (r < M)
                *(float2*)(g_h1 + (size_t)r * 256 + cg) = make_float2(C[mt][nt][0], C[mt][nt][1]);
            if (r + 8 < M)
                *(float2*)(g_h1 + (size_t)(r + 8) * 256 + cg) = make_float2(C[mt][nt][2], C[mt][nt][3]);
        }
#pragma unroll
        for (int o = 1; o <= 2; o <<= 1) {
#pragma unroll
            for (int hs = 0; hs < 2; hs++)
#pragma unroll
                for (int ri = 0; ri < 2; ri++) {
                    ps[hs][ri] += __shfl_xor_sync(0xffffffffu, ps[hs][ri], o);
                    pd[hs][ri] += __shfl_xor_sync(0xffffffffu, pd[hs][ri], o);
                }
        }
        if (qc == 0) {
            int headb = (col0 >> 5) + warp_n * 2;
            if (r < M) {
                g_as1[r * 8 + headb]     = ps[0][0];
                g_as1[r * 8 + headb + 1] = ps[1][0];
                g_ad1[r * 8 + headb]     = pd[0][0];
                g_ad1[r * 8 + headb + 1] = pd[1][0];
            }
            if (r + 8 < M) {
                g_as1[(r + 8) * 8 + headb]     = ps[0][1];
                g_as1[(r + 8) * 8 + headb + 1] = ps[1][1];
                g_ad1[(r + 8) * 8 + headb]     = pd[0][1];
                g_ad1[(r + 8) * 8 + headb + 1] = pd[1][1];
            }
        }
    }
}

// ---------------------------------------------------------------------------
// CSR construction (no zero_deg: deg is re-zeroed by gat2 each replay)
// ---------------------------------------------------------------------------
__global__ void count_deg(const int* __restrict__ dst, int E, int ET) {
    int e = blockIdx.x * blockDim.x + threadIdx.x;
    if (e >= ET) return;
    int d = (e < E) ? dst[e] : (e - E);
    atomicAdd(&g_deg[d], 1);
}

__global__ void scan_local(int M) {
    __shared__ int wsum[32];
    int b = blockIdx.x, tid = threadIdx.x, lane = tid & 31, w = tid >> 5;
    int i = b * 1024 + tid;
    int v = (i < M) ? g_deg[i] : 0;
    int x = v;
#pragma unroll
    for (int o = 1; o < 32; o <<= 1) {
        int y = __shfl_up_sync(0xffffffffu, x, o);
        if (lane >= o) x += y;
    }
    if (lane == 31) wsum[w] = x;
    __syncthreads();
    if (w == 0) {
        int s = wsum[lane];
#pragma unroll
        for (int o = 1; o < 32; o <<= 1) {
            int y = __shfl_up_sync(0xffffffffu, s, o);
            if (lane >= o) s += y;
        }
        wsum[lane] = s;
    }
    __syncthreads();
    int excl = (w > 0 ? wsum[w - 1] : 0) + x - v;
    if (i < M) g_rowptr[i] = excl;
    if (tid == 1023) g_btot[b] = wsum[31];
}

__global__ void scan_tops(int nb) {
    if (threadIdx.x == 0) {
        int s = 0;
        for (int j = 0; j < nb; j++) { g_boff[j] = s; s += g_btot[j]; }
    }
}

__global__ void add_off(int M) {
    int b = blockIdx.x;
    int i = b * 1024 + threadIdx.x;
    if (i < M) {
        int v = g_rowptr[i] + g_boff[b];
        g_rowptr[i] = v;
        g_cursor[i] = v;
    }
}

__global__ void scatter_csr(const int* __restrict__ src, const int* __restrict__ dst,
                            int E, int ET) {
    int e = blockIdx.x * blockDim.x + threadIdx.x;
    if (e >= ET) return;
    int s, d;
    if (e < E) { s = src[e]; d = dst[e]; } else { s = e - E; d = s; }
    int pos = atomicAdd(&g_cursor[d], 1);
    g_csr[pos] = s;
}

// ---------------------------------------------------------------------------
// Layer-1 fused: warp per dst node, channels in registers.
// No-max softmax (logits bounded ~8 << 88): plain exp, per-lane deferred
// denominator, zero per-chunk reductions, no acc rescaling.
// ---------------------------------------------------------------------------
__global__ __launch_bounds__(256)
void gat1_fused(const float* __restrict__ b1, int M) {
    __shared__ float s_w[8 * 256];
    int lane = threadIdx.x & 31, w = threadIdx.x >> 5;
    int node = blockIdx.x * 8 + w;
    if (node >= M) return;
    float* sw = s_w + w * 256;
    int hl = lane >> 2;

    float4 d0 = *(const float4*)(g_ad1 + (size_t)node * HH);
    float4 d1 = *(const float4*)(g_ad1 + (size_t)node * HH + 4);
    float adst[8] = {d0.x, d0.y, d0.z, d0.w, d1.x, d1.y, d1.z, d1.w};

    int start = g_rowptr[node];
    int deg   = g_deg[node];

    float den[8], acc[8];
#pragma unroll
    for (int h = 0; h < 8; h++) { den[h] = 0.f; acc[h] = 0.f; }

    for (int base = 0; base < deg; base += 32) {
        int nE = min(32, deg - base);
        int s = 0;
        float ex[8];
        if (lane < nE) {
            s = g_csr[start + base + lane];
            float4 a0 = *(const float4*)(g_as1 + (size_t)s * HH);
            float4 a1 = *(const float4*)(g_as1 + (size_t)s * HH + 4);
            float as[8] = {a0.x, a0.y, a0.z, a0.w, a1.x, a1.y, a1.z, a1.w};
#pragma unroll
            for (int h = 0; h < 8; h++) {
                float v = as[h] + adst[h];
                v = v > 0.f ? v : 0.2f * v;
                ex[h] = __expf(v);
            }
        } else {
#pragma unroll
            for (int h = 0; h < 8; h++) ex[h] = 0.f;
        }
#pragma unroll
        for (int h = 0; h < 8; h++) {
            den[h] += ex[h];
            sw[h * 32 + ((lane + h * 4) & 31)] = ex[h];
        }
        __syncwarp();

        const float* hbase = g_h1 + (size_t)lane * 8;
        int e = 0;
        for (; e + 4 <= nE; e += 4) {
            int s0 = __shfl_sync(0xffffffffu, s, e);
            int s1 = __shfl_sync(0xffffffffu, s, e + 1);
            int s2 = __shfl_sync(0xffffffffu, s, e + 2);
            int s3 = __shfl_sync(0xffffffffu, s, e + 3);
            float w0 = sw[hl * 32 + ((e     + hl * 4) & 31)];
            float w1 = sw[hl * 32 + ((e + 1 + hl * 4) & 31)];
            float w2 = sw[hl * 32 + ((e + 2 + hl * 4) & 31)];
            float w3 = sw[hl * 32 + ((e + 3 + hl * 4) & 31)];
            const float4* p0 = (const float4*)(hbase + (size_t)s0 * 256);
            const float4* p1 = (const float4*)(hbase + (size_t)s1 * 256);
            const float4* p2 = (const float4*)(hbase + (size_t)s2 * 256);
            const float4* p3 = (const float4*)(hbase + (size_t)s3 * 256);
            float4 u0 = p0[0], u1 = p0[1];
            float4 v0 = p1[0], v1 = p1[1];
            float4 x0 = p2[0], x1 = p2[1];
            float4 y0 = p3[0], y1 = p3[1];
            acc[0] += u0.x * w0 + v0.x * w1 + x0.x * w2 + y0.x * w3;
            acc[1] += u0.y * w0 + v0.y * w1 + x0.y * w2 + y0.y * w3;
            acc[2] += u0.z * w0 + v0.z * w1 + x0.z * w2 + y0.z * w3;
            acc[3] += u0.w * w0 + v0.w * w1 + x0.w * w2 + y0.w * w3;
            acc[4] += u1.x * w0 + v1.x * w1 + x1.x * w2 + y1.x * w3;
            acc[5] += u1.y * w0 + v1.y * w1 + x1.y * w2 + y1.y * w3;
            acc[6] += u1.z * w0 + v1.z * w1 + x1.z * w2 + y1.z * w3;
            acc[7] += u1.w * w0 + v1.w * w1 + x1.w * w2 + y1.w * w3;
        }
        for (; e < nE; e++) {
            int s0 = __shfl_sync(0xffffffffu, s, e);
            float w0 = sw[hl * 32 + ((e + hl * 4) & 31)];
            const float4* p0 = (const float4*)(hbase + (size_t)s0 * 256);
            float4 u0 = p0[0], u1 = p0[1];
            acc[0] += u0.x * w0; acc[1] += u0.y * w0;
            acc[2] += u0.z * w0; acc[3] += u0.w * w0;
            acc[4] += u1.x * w0; acc[5] += u1.y * w0;
            acc[6] += u1.z * w0; acc[7] += u1.w * w0;
        }
        __syncwarp();
    }

    // single deferred denominator reduction per node
#pragma unroll
    for (int h = 0; h < 8; h++) {
        float d = den[h];
#pragma unroll
        for (int o = 16; o > 0; o >>= 1)
            d += __shfl_xor_sync(0xffffffffu, d, o);
        den[h] = d;
    }
    float dsel = den[0];
#pragma unroll
    for (int h = 1; h < 8; h++) if (hl == h) dsel = den[h];
    float inv = 1.f / (dsel + 1e-16f);
    uint32_t oh[4], ol[4];
#pragma unroll
    for (int i = 0; i < 4; i++) {
        float o0 = acc[2 * i]     * inv + __ldg(b1 + lane * 8 + 2 * i);
        float o1 = acc[2 * i + 1] * inv + __ldg(b1 + lane * 8 + 2 * i + 1);
        o0 = o0 > 0.f ? o0 : expm1f(o0);
        o1 = o1 > 0.f ? o1 : expm1f(o1);
        split2(o0, o1, oh[i], ol[i]);
    }
    g_o1h[(size_t)node * 32 + lane] = make_uint4(oh[0], oh[1], oh[2], oh[3]);
    g_o1l[(size_t)node * 32 + lane] = make_uint4(ol[0], ol[1], ol[2], ol[3]);
}

// ---------------------------------------------------------------------------
// GEMM2 (tensor cores, register-only) + fused a2 projection
// ---------------------------------------------------------------------------
__global__ __launch_bounds__(256)
void mma_gemm2(const float* __restrict__ att_s, const float* __restrict__ att_d, int M) {
    int lane = threadIdx.x & 31, w = threadIdx.x >> 5;
    int g = lane >> 2, t = lane & 3;
    int rA  = blockIdx.x * 128 + w * 16 + g;
    int rA8 = rA + 8;
    int rAc  = min(rA,  M - 1);
    int rA8c = min(rA8, M - 1);

    const uint32_t* Ah = (const uint32_t*)g_o1h;
    const uint32_t* Al = (const uint32_t*)g_o1l;
    const uint32_t* p0h = Ah + (size_t)rAc  * 128 + t;
    const uint32_t* p1h = Ah + (size_t)rA8c * 128 + t;
    const uint32_t* p0l = Al + (size_t)rAc  * 128 + t;
    const uint32_t* p1l = Al + (size_t)rA8c * 128 + t;

    float C[5][4];
#pragma unroll
    for (int nt = 0; nt < 5; nt++)
#pragma unroll
        for (int i = 0; i < 4; i++) C[nt][i] = 0.f;

#pragma unroll
    for (int kk2 = 0; kk2 < 128; kk2 += 8) {
        uint32_t ah[4], al[4];
        ah[0] = p0h[kk2];     ah[1] = p1h[kk2];
        ah[2] = p0h[kk2 + 4]; ah[3] = p1h[kk2 + 4];
        al[0] = p0l[kk2];     al[1] = p1l[kk2];
        al[2] = p0l[kk2 + 4]; al[3] = p1l[kk2 + 4];
#pragma unroll
        for (int nt = 0; nt < 5; nt++) {
            int nb = (nt * 8 + g) * 128 + kk2 + t;
            uint32_t bh[2] = { g_W2t_hi[nb], g_W2t_hi[nb + 4] };
            uint32_t bl[2] = { g_W2t_lo[nb], g_W2t_lo[nb + 4] };
            mma16816(C[nt], ah, bh);
            mma16816(C[nt], ah, bl);
            mma16816(C[nt], al, bh);
        }
    }

    float ps0 = 0.f, pd0 = 0.f, ps1 = 0.f, pd1 = 0.f;
#pragma unroll
    for (int nt = 0; nt < 5; nt++) {
        int col = nt * 8 + t * 2;
        float s0 = __ldg(att_s + col), s1 = __ldg(att_s + col + 1);
        float e0 = __ldg(att_d + col), e1 = __ldg(att_d + col + 1);
        ps0 += C[nt][0] * s0 + C[nt][1] * s1;
        pd0 += C[nt][0] * e0 + C[nt][1] * e1;
        ps1 += C[nt][2] * s0 + C[nt][3] * s1;
        pd1 += C[nt][2] * e0 + C[nt][3] * e1;
        if (rA < M)
            *(float2*)(g_h2 + (size_t)rA * OUTC + col) = make_float2(C[nt][0], C[nt][1]);
        if (rA8 < M)
            *(float2*)(g_h2 + (size_t)rA8 * OUTC + col) = make_float2(C[nt][2], C[nt][3]);
    }
#pragma unroll
    for (int o = 1; o <= 2; o <<= 1) {
        ps0 += __shfl_xor_sync(0xffffffffu, ps0, o);
        pd0 += __shfl_xor_sync(0xffffffffu, pd0, o);
        ps1 += __shfl_xor_sync(0xffffffffu, ps1, o);
        pd1 += __shfl_xor_sync(0xffffffffu, pd1, o);
    }
    if (t == 0) {
        if (rA < M)  { g_as2[rA]  = ps0; g_ad2[rA]  = pd0; }
        if (rA8 < M) { g_as2[rA8] = ps1; g_ad2[rA8] = pd1; }
    }
}

// ---------------------------------------------------------------------------
// Layer-2 fused (no-max softmax, deferred denominator). Warp per dst node.
// Also re-zeroes g_deg after last use (replaces zero_deg kernel).
// ---------------------------------------------------------------------------
__global__ __launch_bounds__(256)
void gat2_fused(float* __restrict__ out, const float* __restrict__ b2, int M) {
    int gw = (blockIdx.x * blockDim.x + threadIdx.x) >> 5;
    if (gw >= M) return;
    int lane = threadIdx.x & 31;

    int start = g_rowptr[gw];
    int deg   = g_deg[gw];
    if (lane == 0) g_deg[gw] = 0;            // reset for next replay
    float ad = g_ad2[gw];
    float den_l = 0.f, acc0 = 0.f, acc1 = 0.f;

    for (int base = 0; base < deg; base += 32) {
        int nE = min(32, deg - base);
        int s = 0;
        float ex = 0.f;
        if (lane < nE) {
            s = g_csr[start + base + lane];
            float t = g_as2[s] + ad;
            t = t > 0.f ? t : 0.2f * t;
            ex = __expf(t);
        }
        den_l += ex;
        for (int e = 0; e < nE; e++) {
            float a  = __shfl_sync(0xffffffffu, ex, e);
            int   se = __shfl_sync(0xffffffffu, s, e);
            const float* r = g_h2 + (size_t)se * OUTC;
            acc0 += r[lane] * a;
            if (lane < 8) acc1 += r[32 + lane] * a;
        }
    }
    float den = den_l;
#pragma unroll
    for (int o = 16; o > 0; o >>= 1)
        den += __shfl_xor_sync(0xffffffffu, den, o);
    float inv = 1.f / (den + 1e-16f);
    out[(size_t)gw * OUTC + lane] = acc0 * inv + __ldg(b2 + lane);
    if (lane < 8)
        out[(size_t)gw * OUTC + 32 + lane] = acc1 * inv + __ldg(b2 + 32 + lane);
}

// ---------------------------------------------------------------------------
// Launcher: fork-join; mma_gemm1 as 4th call (the profiled slot)
// ---------------------------------------------------------------------------
extern "C" void kernel_launch(void* const* d_in, const int* in_sizes, int n_in,
                              void* d_out, int out_size) {
    const float* x      = (const float*)d_in[0];
    const int*   ei     = (const int*)  d_in[1];
    const float* W1     = (const float*)d_in[2];
    const float* att_s1 = (const float*)d_in[3];
    const float* att_d1 = (const float*)d_in[4];
    const float* b1     = (const float*)d_in[5];
    const float* W2     = (const float*)d_in[6];
    const float* att_s2 = (const float*)d_in[7];
    const float* att_d2 = (const float*)d_in[8];
    const float* b2     = (const float*)d_in[9];
    float* out = (float*)d_out;

    int M  = in_sizes[0] / F1;
    int E  = in_sizes[1] / 2;
    int ET = E + M;
    int eb = (ET + 255) / 256;
    int nb = (M + 1023) / 1024;

    static cudaStream_t s2 = nullptr;
    static cudaEvent_t ev_fork = nullptr, ev_join = nullptr;
    if (s2 == nullptr) {
        cudaStreamCreateWithFlags(&s2, cudaStreamNonBlocking);
        cudaEventCreateWithFlags(&ev_fork, cudaEventDisableTiming);
        cudaEventCreateWithFlags(&ev_join, cudaEventDisableTiming);
    }

    // fork
    cudaEventRecord(ev_fork, 0);
    cudaStreamWaitEvent(s2, ev_fork, 0);

    prep_W<<<128, 256>>>(W1);                                            // call 1 (s0)
    count_deg<<<eb, 256, 0, s2>>>(ei + E, E, ET);                        // call 2 (s2)
    scan_local<<<nb, 1024, 0, s2>>>(M);                                  // call 3 (s2)
    mma_gemm1<<<dim3(2, (M + 127) / 128), 256>>>(x, att_s1, att_d1, M);  // call 4 (s0) <- profiled
    scan_tops<<<1, 32, 0, s2>>>(nb);                                     // call 5 (s2)
    add_off<<<nb, 1024, 0, s2>>>(M);                                     // call 6 (s2)
    scatter_csr<<<eb, 256, 0, s2>>>(ei, ei + E, E, ET);                  // call 7 (s2)
    prep_W2<<<20, 256, 0, s2>>>(W2);                                     // call 8 (s2)
    cudaEventRecord(ev_join, s2);

    // join
    cudaStreamWaitEvent(0, ev_join, 0);

    gat1_fused<<<(M + 7) / 8, 256>>>(b1, M);                             // call 9
    mma_gemm2<<<(M + 127) / 128, 256>>>(att_s2, att_d2, M);              // call 10
    gat2_fused<<<(M * 32 + 255) / 256, 256>>>(out, b2, M);               // call 11
}

// round 14
// speedup vs baseline: 1.2129x; 1.2069x over previous
#include <cuda_runtime.h>
#include <cuda_bf16.h>
#include <math.h>
#include <stdint.h>

// ---------------------------------------------------------------------------
// Problem constants
// ---------------------------------------------------------------------------
#define MAXN 100000
#define MAXE 800000
#define MAXET (MAXE + MAXN)
#define F1 256
#define HH 8
#define OUTC 40

// ---------------------------------------------------------------------------
// Scratch
// ---------------------------------------------------------------------------
__device__ float g_h1 [(size_t)MAXN * F1];     // x @ W1 (fp32, gathered in layer 1)
__device__ uint4 g_o1h[(size_t)MAXN * 32];     // out1 bf16 hi
__device__ uint4 g_o1l[(size_t)MAXN * 32];     // out1 bf16 lo
__device__ float g_h2 [(size_t)MAXN * OUTC];
__device__ float g_as1[MAXN * HH];
__device__ float g_ad1[MAXN * HH];
__device__ float g_as2[MAXN];
__device__ float g_ad2[MAXN];

// W1^T bf16 hi/lo, FRAGMENT-CONTIGUOUS layout:
// fragment f(ch, n8, k16) = 64 uint32 (256B); lane reads uint2 at frag+lane*8.
__device__ uint32_t g_W1f_hi[256 * 128];
__device__ uint32_t g_W1f_lo[256 * 128];
// W2^T bf16 hi/lo, [n=40][k2=128]
__device__ uint32_t g_W2t_hi[40 * 128];
__device__ uint32_t g_W2t_lo[40 * 128];

// CSR by destination
__device__ int g_deg   [MAXN];
__device__ int g_rowptr[MAXN];
__device__ int g_cursor[MAXN];
__device__ int g_csr   [MAXET];
__device__ int g_btot  [128];
__device__ int g_boff  [128];

// ---------------------------------------------------------------------------
// Helpers
// ---------------------------------------------------------------------------
__device__ __forceinline__ void split2(float a, float b, uint32_t& hi, uint32_t& lo) {
    __nv_bfloat16 ha = __float2bfloat16(a);
    __nv_bfloat16 hb = __float2bfloat16(b);
    __nv_bfloat16 la = __float2bfloat16(a - __bfloat162float(ha));
    __nv_bfloat16 lb = __float2bfloat16(b - __bfloat162float(hb));
    __nv_bfloat162 h = __halves2bfloat162(ha, hb);
    __nv_bfloat162 l = __halves2bfloat162(la, lb);
    hi = *reinterpret_cast<uint32_t*>(&h);
    lo = *reinterpret_cast<uint32_t*>(&l);
}

__device__ __forceinline__ void ldsm4(uint32_t* r, uint32_t addr) {
    asm volatile("ldmatrix.sync.aligned.m8n8.x4.shared.b16 {%0,%1,%2,%3}, [%4];"
        : "=r"(r[0]), "=r"(r[1]), "=r"(r[2]), "=r"(r[3]) : "r"(addr));
}

__device__ __forceinline__ void mma16816(float* c, const uint32_t* a, const uint32_t* b) {
    asm volatile(
        "mma.sync.aligned.m16n8k16.row.col.f32.bf16.bf16.f32 "
        "{%0,%1,%2,%3}, {%4,%5,%6,%7}, {%8,%9}, {%0,%1,%2,%3};\n"
        : "+f"(c[0]), "+f"(c[1]), "+f"(c[2]), "+f"(c[3])
        : "r"(a[0]), "r"(a[1]), "r"(a[2]), "r"(a[3]), "r"(b[0]), "r"(b[1]));
}

// ---------------------------------------------------------------------------
// Weight prep: W1 [k=256][n=256] -> fragment-contiguous bf16 hi/lo
// ---------------------------------------------------------------------------
__global__ void prep_W(const float* __restrict__ W) {
    int t = blockIdx.x * blockDim.x + threadIdx.x;
    if (t >= 256 * 128) return;
    int n = t >> 7, j = t & 127;            // n = output col, j = k2 index
    uint32_t h, l;
    split2(W[(size_t)(2 * j) * 256 + n], W[(size_t)(2 * j + 1) * 256 + n], h, l);
    int ch = n >> 7, nh = n & 127;
    int n8 = nh >> 3, ncol = nh & 7;
    int k16 = j >> 3, kp = (j >> 2) & 1, bt = j & 3;
    int lane = ncol * 4 + bt;
    int idx = (((ch * 16 + n8) * 16 + k16) * 32 + lane) * 2 + kp;
    g_W1f_hi[idx] = h;
    g_W1f_lo[idx] = l;
}

__global__ void prep_W2(const float* __restrict__ W2) {  // W2 [256][40]
    int t = blockIdx.x * blockDim.x + threadIdx.x;
    if (t >= 40 * 128) return;
    int n = t >> 7, k2 = t & 127, k = k2 * 2;
    uint32_t h, l;
    split2(W2[(size_t)k * OUTC + n], W2[(size_t)(k + 1) * OUTC + n], h, l);
    g_W2t_hi[n * 128 + k2] = h;
    g_W2t_lo[n * 128 + k2] = l;
}

// ---------------------------------------------------------------------------
// GEMM1 (tensor cores): g_h1[M,256] = x[M,256] @ W1[256,256], bf16 split.
// A through smem (in-loop fp32->bf16 split); B fragments direct from global
// in FRAGMENT-CONTIGUOUS order: each warp B-load = one coalesced 256B txn.
// Fused a1 projection in the epilogue.
// ---------------------------------------------------------------------------
__global__ __launch_bounds__(256, 2)
void mma_gemm1(const float* __restrict__ A,
               const float* __restrict__ att_s, const float* __restrict__ att_d, int M) {
    __shared__ uint4 As_hi[512], As_lo[512];   // 128 rows x 4 chunks (16B)

    int tid = threadIdx.x;
    int lane = tid & 31, w = tid >> 5;
    int warp_m = w & 3, warp_n = w >> 2;
    int row0 = blockIdx.y * 128;
    int col0 = blockIdx.x * 128;

    uint32_t as_hi_b = (uint32_t)__cvta_generic_to_shared(As_hi);
    uint32_t as_lo_b = (uint32_t)__cvta_generic_to_shared(As_lo);

    const uint2* Wfh = (const uint2*)g_W1f_hi;
    const uint2* Wfl = (const uint2*)g_W1f_lo;
    int half16 = blockIdx.x * 16;              // fragment block for this col-half

    float C[2][8][4];
#pragma unroll
    for (int mt = 0; mt < 2; mt++)
#pragma unroll
        for (int nt = 0; nt < 8; nt++)
#pragma unroll
            for (int i = 0; i < 4; i++) C[mt][nt][i] = 0.f;

    int lr = lane & 15, lh = lane >> 4;

    for (int kc = 0; kc < 8; kc++) {
        int k0 = kc * 32;
        __syncthreads();
        // ---- A tile: load fp32, convert to bf16 hi/lo, swizzled store ----
#pragma unroll
        for (int j = 0; j < 2; j++) {
            int cid = j * 256 + tid;          // 0..511
            int row = cid >> 2;
            int ch  = cid & 3;
            int gr = row0 + row;
            float4 f0 = make_float4(0.f, 0.f, 0.f, 0.f), f1 = f0;
            if (gr < M) {
                const float4* p = (const float4*)(A + (size_t)gr * 256 + k0 + ch * 8);
                f0 = p[0]; f1 = p[1];
            }
            uint32_t h[4], l[4];
            split2(f0.x, f0.y, h[0], l[0]);
            split2(f0.z, f0.w, h[1], l[1]);
            split2(f1.x, f1.y, h[2], l[2]);
            split2(f1.z, f1.w, h[3], l[3]);
            int off = row * 4 + (ch ^ (row & 3));
            As_hi[off] = make_uint4(h[0], h[1], h[2], h[3]);
            As_lo[off] = make_uint4(l[0], l[1], l[2], l[3]);
        }
        __syncthreads();

#pragma unroll
        for (int ks = 0; ks < 2; ks++) {
            int kk2 = ks * 2;
            int blk = kc * 2 + ks;             // k16 block index (0..15)
            uint32_t a_hi[2][4], a_lo[2][4];
#pragma unroll
            for (int mt = 0; mt < 2; mt++) {
                int r = warp_m * 32 + mt * 16 + lr;
                int c = kk2 + lh;
                uint32_t bo = (uint32_t)(r * 4 + (c ^ (r & 3))) * 16;
                ldsm4(a_hi[mt], as_hi_b + bo);
                ldsm4(a_lo[mt], as_lo_b + bo);
            }
#pragma unroll
            for (int ng = 0; ng < 4; ng++) {
                int n8a = warp_n * 8 + ng * 2;       // two n8 fragments
                size_t f0 = ((size_t)(half16 + n8a) * 16 + blk) * 32 + lane;
                size_t f1 = f0 + 16 * 32;            // n8a+1
                uint2 bh0 = Wfh[f0], bh1 = Wfh[f1];
                uint2 bl0 = Wfl[f0], bl1 = Wfl[f1];
                uint32_t rbh0[2] = {bh0.x, bh0.y}, rbh1[2] = {bh1.x, bh1.y};
                uint32_t rbl0[2] = {bl0.x, bl0.y}, rbl1[2] = {bl1.x, bl1.y};
                int nt0 = ng * 2, nt1 = ng * 2 + 1;
#pragma unroll
                for (int mt = 0; mt < 2; mt++) {
                    mma16816(C[mt][nt0], a_hi[mt], rbh0);
                    mma16816(C[mt][nt0], a_hi[mt], rbl0);
                    mma16816(C[mt][nt0], a_lo[mt], rbh0);
                    mma16816(C[mt][nt1], a_hi[mt], rbh1);
                    mma16816(C[mt][nt1], a_hi[mt], rbl1);
                    mma16816(C[mt][nt1], a_lo[mt], rbh1);
                }
            }
        }
    }

    // ---- epilogue: store h1 + fused a1 projection ----
    int qr = lane >> 2, qc = lane & 3;
#pragma unroll
    for (int mt = 0; mt < 2; mt++) {
        int r = row0 + warp_m * 32 + mt * 16 + qr;
        float ps[2][2] = {{0.f, 0.f}, {0.f, 0.f}};  // [head_sel][row_inst]
        float pd[2][2] = {{0.f, 0.f}, {0.f, 0.f}};
#pragma unroll
        for (int nt = 0; nt < 8; nt++) {
            int cg = col0 + warp_n * 64 + nt * 8 + qc * 2;
            int hs = nt >> 2;
            float s0 = __ldg(att_s + cg), s1 = __ldg(att_s + cg + 1);
            float e0 = __ldg(att_d + cg), e1 = __ldg(att_d + cg + 1);
            ps[hs][0] += C[mt][nt][0] * s0 + C[mt][nt][1] * s1;
            pd[hs][0] += C[mt][nt][0] * e0 + C[mt][nt][1] * e1;
            ps[hs][1] += C[mt][nt][2] * s0 + C[mt][nt][3] * s1;
            pd[hs][1] += C[mt][nt][2] * e0 + C[mt][nt][3] * e1;
            if (r < M)
                *(float2*)(g_h1 + (size_t)r * 256 + cg) = make_float2(C[mt][nt][0], C[mt][nt][1]);
            if (r + 8 < M)
                *(float2*)(g_h1 + (size_t)(r + 8) * 256 + cg) = make_float2(C[mt][nt][2], C[mt][nt][3]);
        }
#pragma unroll
        for (int o = 1; o <= 2; o <<= 1) {
#pragma unroll
            for (int hs = 0; hs < 2; hs++)
#pragma unroll
                for (int ri = 0; ri < 2; ri++) {
                    ps[hs][ri] += __shfl_xor_sync(0xffffffffu, ps[hs][ri], o);
                    pd[hs][ri] += __shfl_xor_sync(0xffffffffu, pd[hs][ri], o);
                }
        }
        if (qc == 0) {
            int headb = (col0 >> 5) + warp_n * 2;
            if (r < M) {
                g_as1[r * 8 + headb]     = ps[0][0];
                g_as1[r * 8 + headb + 1] = ps[1][0];
                g_ad1[r * 8 + headb]     = pd[0][0];
                g_ad1[r * 8 + headb + 1] = pd[1][0];
            }
            if (r + 8 < M) {
                g_as1[(r + 8) * 8 + headb]     = ps[0][1];
                g_as1[(r + 8) * 8 + headb + 1] = ps[1][1];
                g_ad1[(r + 8) * 8 + headb]     = pd[0][1];
                g_ad1[(r + 8) * 8 + headb + 1] = pd[1][1];
            }
        }
    }
}

// ---------------------------------------------------------------------------
// CSR construction
// ---------------------------------------------------------------------------
__global__ void zero_deg(int M) {
    int i = blockIdx.x * blockDim.x + threadIdx.x;
    if (i < M) g_deg[i] = 0;
}

__global__ void count_deg(const int* __restrict__ dst, int E, int ET) {
    int e = blockIdx.x * blockDim.x + threadIdx.x;
    if (e >= ET) return;
    int d = (e < E) ? dst[e] : (e - E);
    atomicAdd(&g_deg[d], 1);
}

__global__ void scan_local(int M) {
    __shared__ int wsum[32];
    int b = blockIdx.x, tid = threadIdx.x, lane = tid & 31, w = tid >> 5;
    int i = b * 1024 + tid;
    int v = (i < M) ? g_deg[i] : 0;
    int x = v;
#pragma unroll
    for (int o = 1; o < 32; o <<= 1) {
        int y = __shfl_up_sync(0xffffffffu, x, o);
        if (lane >= o) x += y;
    }
    if (lane == 31) wsum[w] = x;
    __syncthreads();
    if (w == 0) {
        int s = wsum[lane];
#pragma unroll
        for (int o = 1; o < 32; o <<= 1) {
            int y = __shfl_up_sync(0xffffffffu, s, o);
            if (lane >= o) s += y;
        }
        wsum[lane] = s;
    }
    __syncthreads();
    int excl = (w > 0 ? wsum[w - 1] : 0) + x - v;
    if (i < M) g_rowptr[i] = excl;
    if (tid == 1023) g_btot[b] = wsum[31];
}

__global__ void scan_tops(int nb) {
    if (threadIdx.x == 0) {
        int s = 0;
        for (int j = 0; j < nb; j++) { g_boff[j] = s; s += g_btot[j]; }
    }
}

__global__ void add_off(int M) {
    int b = blockIdx.x;
    int i = b * 1024 + threadIdx.x;
    if (i < M) {
        int v = g_rowptr[i] + g_boff[b];
        g_rowptr[i] = v;
        g_cursor[i] = v;
    }
}

__global__ void scatter_csr(const int* __restrict__ src, const int* __restrict__ dst,
                            int E, int ET) {
    int e = blockIdx.x * blockDim.x + threadIdx.x;
    if (e >= ET) return;
    int s, d;
    if (e < E) { s = src[e]; d = dst[e]; } else { s = e - E; d = s; }
    int pos = atomicAdd(&g_cursor[d], 1);
    g_csr[pos] = s;
}

// ---------------------------------------------------------------------------
// Layer-1 fused: warp per dst node, channels in registers, online softmax.
// ---------------------------------------------------------------------------
__global__ __launch_bounds__(256)
void gat1_fused(const float* __restrict__ b1, int M) {
    __shared__ float s_w[8 * 256];
    int lane = threadIdx.x & 31, w = threadIdx.x >> 5;
    int node = blockIdx.x * 8 + w;
    if (node >= M) return;
    float* sw = s_w + w * 256;
    int hl = lane >> 2;

    float4 d0 = *(const float4*)(g_ad1 + (size_t)node * HH);
    float4 d1 = *(const float4*)(g_ad1 + (size_t)node * HH + 4);
    float adst[8] = {d0.x, d0.y, d0.z, d0.w, d1.x, d1.y, d1.z, d1.w};

    int start = g_rowptr[node];
    int deg   = g_deg[node];

    float m[8], den[8], acc[8];
#pragma unroll
    for (int h = 0; h < 8; h++) { m[h] = -INFINITY; den[h] = 0.f; acc[h] = 0.f; }

    for (int base = 0; base < deg; base += 32) {
        int nE = min(32, deg - base);
        int s = 0;
        float l[8];
        if (lane < nE) {
            s = g_csr[start + base + lane];
            float4 a0 = *(const float4*)(g_as1 + (size_t)s * HH);
            float4 a1 = *(const float4*)(g_as1 + (size_t)s * HH + 4);
            float as[8] = {a0.x, a0.y, a0.z, a0.w, a1.x, a1.y, a1.z, a1.w};
#pragma unroll
            for (int h = 0; h < 8; h++) {
                float v = as[h] + adst[h];
                l[h] = v > 0.f ? v : 0.2f * v;
            }
        } else {
#pragma unroll
            for (int h = 0; h < 8; h++) l[h] = -INFINITY;
        }

        float sc_my = 1.f;
#pragma unroll
        for (int h = 0; h < 8; h++) {
            float mx = l[h];
#pragma unroll
            for (int o = 16; o > 0; o >>= 1)
                mx = fmaxf(mx, __shfl_xor_sync(0xffffffffu, mx, o));
            float nm = fmaxf(m[h], mx);
            float ex = (lane < nE) ? __expf(l[h] - nm) : 0.f;
            float sm = ex;
#pragma unroll
            for (int o = 16; o > 0; o >>= 1)
                sm += __shfl_xor_sync(0xffffffffu, sm, o);
            float sc = __expf(m[h] - nm);
            den[h] = den[h] * sc + sm;
            m[h] = nm;
            if (h == hl) sc_my = sc;
            sw[h * 32 + ((lane + h * 4) & 31)] = ex;
        }
        __syncwarp();
#pragma unroll
        for (int i = 0; i < 8; i++) acc[i] *= sc_my;

        const float* hbase = g_h1 + (size_t)lane * 8;
        int e = 0;
        for (; e + 4 <= nE; e += 4) {
            int s0 = __shfl_sync(0xffffffffu, s, e);
            int s1 = __shfl_sync(0xffffffffu, s, e + 1);
            int s2 = __shfl_sync(0xffffffffu, s, e + 2);
            int s3 = __shfl_sync(0xffffffffu, s, e + 3);
            float w0 = sw[hl * 32 + ((e     + hl * 4) & 31)];
            float w1 = sw[hl * 32 + ((e + 1 + hl * 4) & 31)];
            float w2 = sw[hl * 32 + ((e + 2 + hl * 4) & 31)];
            float w3 = sw[hl * 32 + ((e + 3 + hl * 4) & 31)];
            const float4* p0 = (const float4*)(hbase + (size_t)s0 * 256);
            const float4* p1 = (const float4*)(hbase + (size_t)s1 * 256);
            const float4* p2 = (const float4*)(hbase + (size_t)s2 * 256);
            const float4* p3 = (const float4*)(hbase + (size_t)s3 * 256);
            float4 u0 = p0[0], u1 = p0[1];
            float4 v0 = p1[0], v1 = p1[1];
            float4 x0 = p2[0], x1 = p2[1];
            float4 y0 = p3[0], y1 = p3[1];
            acc[0] += u0.x * w0 + v0.x * w1 + x0.x * w2 + y0.x * w3;
            acc[1] += u0.y * w0 + v0.y * w1 + x0.y * w2 + y0.y * w3;
            acc[2] += u0.z * w0 + v0.z * w1 + x0.z * w2 + y0.z * w3;
            acc[3] += u0.w * w0 + v0.w * w1 + x0.w * w2 + y0.w * w3;
            acc[4] += u1.x * w0 + v1.x * w1 + x1.x * w2 + y1.x * w3;
            acc[5] += u1.y * w0 + v1.y * w1 + x1.y * w2 + y1.y * w3;
            acc[6] += u1.z * w0 + v1.z * w1 + x1.z * w2 + y1.z * w3;
            acc[7] += u1.w * w0 + v1.w * w1 + x1.w * w2 + y1.w * w3;
        }
        for (; e < nE; e++) {
            int s0 = __shfl_sync(0xffffffffu, s, e);
            float w0 = sw[hl * 32 + ((e + hl * 4) & 31)];
            const float4* p0 = (const float4*)(hbase + (size_t)s0 * 256);
            float4 u0 = p0[0], u1 = p0[1];
            acc[0] += u0.x * w0; acc[1] += u0.y * w0;
            acc[2] += u0.z * w0; acc[3] += u0.w * w0;
            acc[4] += u1.x * w0; acc[5] += u1.y * w0;
            acc[6] += u1.z * w0; acc[7] += u1.w * w0;
        }
        __syncwarp();
    }

    float dsel = den[0];
#pragma unroll
    for (int h = 1; h < 8; h++) if (hl == h) dsel = den[h];
    float inv = 1.f / (dsel + 1e-16f);
    uint32_t oh[4], ol[4];
#pragma unroll
    for (int i = 0; i < 4; i++) {
        float o0 = acc[2 * i]     * inv + __ldg(b1 + lane * 8 + 2 * i);
        float o1 = acc[2 * i + 1] * inv + __ldg(b1 + lane * 8 + 2 * i + 1);
        o0 = o0 > 0.f ? o0 : expm1f(o0);
        o1 = o1 > 0.f ? o1 : expm1f(o1);
        split2(o0, o1, oh[i], ol[i]);
    }
    g_o1h[(size_t)node * 32 + lane] = make_uint4(oh[0], oh[1], oh[2], oh[3]);
    g_o1l[(size_t)node * 32 + lane] = make_uint4(ol[0], ol[1], ol[2], ol[3]);
}

// ---------------------------------------------------------------------------
// GEMM2 (tensor cores, register-only) + fused a2 projection
// ---------------------------------------------------------------------------
__global__ __launch_bounds__(256)
void mma_gemm2(const float* __restrict__ att_s, const float* __restrict__ att_d, int M) {
    int lane = threadIdx.x & 31, w = threadIdx.x >> 5;
    int g = lane >> 2, t = lane & 3;
    int rA  = blockIdx.x * 128 + w * 16 + g;
    int rA8 = rA + 8;
    int rAc  = min(rA,  M - 1);
    int rA8c = min(rA8, M - 1);

    const uint32_t* Ah = (const uint32_t*)g_o1h;
    const uint32_t* Al = (const uint32_t*)g_o1l;
    const uint32_t* p0h = Ah + (size_t)rAc  * 128 + t;
    const uint32_t* p1h = Ah + (size_t)rA8c * 128 + t;
    const uint32_t* p0l = Al + (size_t)rAc  * 128 + t;
    const uint32_t* p1l = Al + (size_t)rA8c * 128 + t;

    float C[5][4];
#pragma unroll
    for (int nt = 0; nt < 5; nt++)
#pragma unroll
        for (int i = 0; i < 4; i++) C[nt][i] = 0.f;

#pragma unroll
    for (int kk2 = 0; kk2 < 128; kk2 += 8) {
        uint32_t ah[4], al[4];
        ah[0] = p0h[kk2];     ah[1] = p1h[kk2];
        ah[2] = p0h[kk2 + 4]; ah[3] = p1h[kk2 + 4];
        al[0] = p0l[kk2];     al[1] = p1l[kk2];
        al[2] = p0l[kk2 + 4]; al[3] = p1l[kk2 + 4];
#pragma unroll
        for (int nt = 0; nt < 5; nt++) {
            int nb = (nt * 8 + g) * 128 + kk2 + t;
            uint32_t bh[2] = { g_W2t_hi[nb], g_W2t_hi[nb + 4] };
            uint32_t bl[2] = { g_W2t_lo[nb], g_W2t_lo[nb + 4] };
            mma16816(C[nt], ah, bh);
            mma16816(C[nt], ah, bl);
            mma16816(C[nt], al, bh);
        }
    }

    float ps0 = 0.f, pd0 = 0.f, ps1 = 0.f, pd1 = 0.f;
#pragma unroll
    for (int nt = 0; nt < 5; nt++) {
        int col = nt * 8 + t * 2;
        float s0 = __ldg(att_s + col), s1 = __ldg(att_s + col + 1);
        float e0 = __ldg(att_d + col), e1 = __ldg(att_d + col + 1);
        ps0 += C[nt][0] * s0 + C[nt][1] * s1;
        pd0 += C[nt][0] * e0 + C[nt][1] * e1;
        ps1 += C[nt][2] * s0 + C[nt][3] * s1;
        pd1 += C[nt][2] * e0 + C[nt][3] * e1;
        if (rA < M)
            *(float2*)(g_h2 + (size_t)rA * OUTC + col) = make_float2(C[nt][0], C[nt][1]);
        if (rA8 < M)
            *(float2*)(g_h2 + (size_t)rA8 * OUTC + col) = make_float2(C[nt][2], C[nt][3]);
    }
#pragma unroll
    for (int o = 1; o <= 2; o <<= 1) {
        ps0 += __shfl_xor_sync(0xffffffffu, ps0, o);
        pd0 += __shfl_xor_sync(0xffffffffu, pd0, o);
        ps1 += __shfl_xor_sync(0xffffffffu, ps1, o);
        pd1 += __shfl_xor_sync(0xffffffffu, pd1, o);
    }
    if (t == 0) {
        if (rA < M)  { g_as2[rA]  = ps0; g_ad2[rA]  = pd0; }
        if (rA8 < M) { g_as2[rA8] = ps1; g_ad2[rA8] = pd1; }
    }
}

// ---------------------------------------------------------------------------
// Layer-2 fused softmax + aggregate + bias. Warp per dst node.
// ---------------------------------------------------------------------------
__global__ __launch_bounds__(256)
void gat2_fused(float* __restrict__ out, const float* __restrict__ b2, int M) {
    int gw = (blockIdx.x * blockDim.x + threadIdx.x) >> 5;
    if (gw >= M) return;
    int lane = threadIdx.x & 31;

    int start = g_rowptr[gw];
    int deg   = g_deg[gw];
    float ad = g_ad2[gw];
    float m = -INFINITY, den = 0.f, acc0 = 0.f, acc1 = 0.f;

    for (int base = 0; base < deg; base += 32) {
        int nE = min(32, deg - base);
        int s = 0;
        float lg = -INFINITY;
        if (lane < nE) {
            s = g_csr[start + base + lane];
            float t = g_as2[s] + ad;
            lg = t > 0.f ? t : 0.2f * t;
        }
        float mx = lg;
#pragma unroll
        for (int o = 16; o > 0; o >>= 1)
            mx = fmaxf(mx, __shfl_xor_sync(0xffffffffu, mx, o));
        float nm = fmaxf(m, mx);
        float ex = (lane < nE) ? __expf(lg - nm) : 0.f;
        float sm = ex;
#pragma unroll
        for (int o = 16; o > 0; o >>= 1)
            sm += __shfl_xor_sync(0xffffffffu, sm, o);
        float sc = __expf(m - nm);
        den = den * sc + sm;
        acc0 *= sc;
        acc1 *= sc;
        m = nm;
        for (int e = 0; e < nE; e++) {
            float a  = __shfl_sync(0xffffffffu, ex, e);
            int   se = __shfl_sync(0xffffffffu, s, e);
            const float* r = g_h2 + (size_t)se * OUTC;
            acc0 += r[lane] * a;
            if (lane < 8) acc1 += r[32 + lane] * a;
        }
    }
    float inv = 1.f / (den + 1e-16f);
    out[(size_t)gw * OUTC + lane] = acc0 * inv + __ldg(b2 + lane);
    if (lane < 8)
        out[(size_t)gw * OUTC + 32 + lane] = acc1 * inv + __ldg(b2 + 32 + lane);
}

// ---------------------------------------------------------------------------
// Launcher: fork-join — CSR chain + prep_W2 run concurrently with
// prep_W -> mma_gemm1 on a second captured stream.
// ---------------------------------------------------------------------------
extern "C" void kernel_launch(void* const* d_in, const int* in_sizes, int n_in,
                              void* d_out, int out_size) {
    const float* x      = (const float*)d_in[0];
    const int*   ei     = (const int*)  d_in[1];
    const float* W1     = (const float*)d_in[2];
    const float* att_s1 = (const float*)d_in[3];
    const float* att_d1 = (const float*)d_in[4];
    const float* b1     = (const float*)d_in[5];
    const float* W2     = (const float*)d_in[6];
    const float* att_s2 = (const float*)d_in[7];
    const float* att_d2 = (const float*)d_in[8];
    const float* b2     = (const float*)d_in[9];
    float* out = (float*)d_out;

    int M  = in_sizes[0] / F1;
    int E  = in_sizes[1] / 2;
    int ET = E + M;
    int eb = (ET + 255) / 256;
    int nb = (M + 1023) / 1024;

    static cudaStream_t s2 = nullptr;
    static cudaEvent_t ev_fork = nullptr, ev_join = nullptr;
    if (s2 == nullptr) {
        cudaStreamCreateWithFlags(&s2, cudaStreamNonBlocking);
        cudaEventCreateWithFlags(&ev_fork, cudaEventDisableTiming);
        cudaEventCreateWithFlags(&ev_join, cudaEventDisableTiming);
    }

    // fork
    cudaEventRecord(ev_fork, 0);
    cudaStreamWaitEvent(s2, ev_fork, 0);

    // main stream: W1 prep + GEMM1 (the heavy compute)
    prep_W<<<128, 256>>>(W1);
    mma_gemm1<<<dim3(2, (M + 127) / 128), 256>>>(x, att_s1, att_d1, M);

    // side stream: CSR build + W2 prep (independent of GEMM1)
    zero_deg<<<(M + 255) / 256, 256, 0, s2>>>(M);
    count_deg<<<eb, 256, 0, s2>>>(ei + E, E, ET);
    scan_local<<<nb, 1024, 0, s2>>>(M);
    scan_tops<<<1, 32, 0, s2>>>(nb);
    add_off<<<nb, 1024, 0, s2>>>(M);
    scatter_csr<<<eb, 256, 0, s2>>>(ei, ei + E, E, ET);
    prep_W2<<<20, 256, 0, s2>>>(W2);
    cudaEventRecord(ev_join, s2);

    // join
    cudaStreamWaitEvent(0, ev_join, 0);

    // layer 1 edge phase + layer 2
    gat1_fused<<<(M + 7) / 8, 256>>>(b1, M);
    mma_gemm2<<<(M + 127) / 128, 256>>>(att_s2, att_d2, M);
    gat2_fused<<<(M * 32 + 255) / 256, 256>>>(out, b2, M);
}

// round 15
// speedup vs baseline: 1.2757x; 1.0517x over previous
#include <cuda_runtime.h>
#include <cuda_bf16.h>
#include <math.h>
#include <stdint.h>

// ---------------------------------------------------------------------------
// Problem constants
// ---------------------------------------------------------------------------
#define MAXN 100000
#define MAXE 800000
#define MAXET (MAXE + MAXN)
#define F1 256
#define HH 8
#define OUTC 40

// ---------------------------------------------------------------------------
// Scratch
// ---------------------------------------------------------------------------
__device__ float g_h1 [(size_t)MAXN * F1];     // x @ W1 (fp32, gathered in layer 1)
__device__ uint4 g_o1h[(size_t)MAXN * 32];     // out1 bf16 hi
__device__ uint4 g_o1l[(size_t)MAXN * 32];     // out1 bf16 lo
__device__ float g_h2 [(size_t)MAXN * OUTC];
__device__ float g_as1[MAXN * HH];
__device__ float g_ad1[MAXN * HH];
__device__ float g_as2[MAXN];
__device__ float g_ad2[MAXN];

// W1^T bf16 hi/lo, FRAGMENT-CONTIGUOUS layout:
// fragment f(ch, n8, k16) = 64 uint32 (256B); lane reads uint2 at frag+lane*8.
__device__ uint32_t g_W1f_hi[256 * 128];
__device__ uint32_t g_W1f_lo[256 * 128];
// W2^T bf16 hi/lo, [n=40][k2=128]
__device__ uint32_t g_W2t_hi[40 * 128];
__device__ uint32_t g_W2t_lo[40 * 128];

// CSR by destination
__device__ int g_deg   [MAXN];
__device__ int g_rowptr[MAXN];
__device__ int g_cursor[MAXN];
__device__ int g_csr   [MAXET];
__device__ int g_btot  [128];
__device__ int g_boff  [128];

// ---------------------------------------------------------------------------
// Helpers
// ---------------------------------------------------------------------------
__device__ __forceinline__ void split2(float a, float b, uint32_t& hi, uint32_t& lo) {
    __nv_bfloat16 ha = __float2bfloat16(a);
    __nv_bfloat16 hb = __float2bfloat16(b);
    __nv_bfloat16 la = __float2bfloat16(a - __bfloat162float(ha));
    __nv_bfloat16 lb = __float2bfloat16(b - __bfloat162float(hb));
    __nv_bfloat162 h = __halves2bfloat162(ha, hb);
    __nv_bfloat162 l = __halves2bfloat162(la, lb);
    hi = *reinterpret_cast<uint32_t*>(&h);
    lo = *reinterpret_cast<uint32_t*>(&l);
}

__device__ __forceinline__ void ldsm4(uint32_t* r, uint32_t addr) {
    asm volatile("ldmatrix.sync.aligned.m8n8.x4.shared.b16 {%0,%1,%2,%3}, [%4];"
        : "=r"(r[0]), "=r"(r[1]), "=r"(r[2]), "=r"(r[3]) : "r"(addr));
}

__device__ __forceinline__ void mma16816(float* c, const uint32_t* a, const uint32_t* b) {
    asm volatile(
        "mma.sync.aligned.m16n8k16.row.col.f32.bf16.bf16.f32 "
        "{%0,%1,%2,%3}, {%4,%5,%6,%7}, {%8,%9}, {%0,%1,%2,%3};\n"
        : "+f"(c[0]), "+f"(c[1]), "+f"(c[2]), "+f"(c[3])
        : "r"(a[0]), "r"(a[1]), "r"(a[2]), "r"(a[3]), "r"(b[0]), "r"(b[1]));
}

// ---------------------------------------------------------------------------
// Weight prep: W1 [k=256][n=256] -> fragment-contiguous bf16 hi/lo
// ---------------------------------------------------------------------------
__global__ void prep_W(const float* __restrict__ W) {
    int t = blockIdx.x * blockDim.x + threadIdx.x;
    if (t >= 256 * 128) return;
    int n = t >> 7, j = t & 127;            // n = output col, j = k2 index
    uint32_t h, l;
    split2(W[(size_t)(2 * j) * 256 + n], W[(size_t)(2 * j + 1) * 256 + n], h, l);
    int ch = n >> 7, nh = n & 127;
    int n8 = nh >> 3, ncol = nh & 7;
    int k16 = j >> 3, kp = (j >> 2) & 1, bt = j & 3;
    int lane = ncol * 4 + bt;
    int idx = (((ch * 16 + n8) * 16 + k16) * 32 + lane) * 2 + kp;
    g_W1f_hi[idx] = h;
    g_W1f_lo[idx] = l;
}

__global__ void prep_W2(const float* __restrict__ W2) {  // W2 [256][40]
    int t = blockIdx.x * blockDim.x + threadIdx.x;
    if (t >= 40 * 128) return;
    int n = t >> 7, k2 = t & 127, k = k2 * 2;
    uint32_t h, l;
    split2(W2[(size_t)k * OUTC + n], W2[(size_t)(k + 1) * OUTC + n], h, l);
    g_W2t_hi[n * 128 + k2] = h;
    g_W2t_lo[n * 128 + k2] = l;
}

// ---------------------------------------------------------------------------
// GEMM1 (tensor cores): g_h1[M,256] = x[M,256] @ W1[256,256], bf16 split.
// A through smem; B fragments direct from global, fragment-contiguous.
// Fused a1 projection in the epilogue. (ncu-verified 144us)
// ---------------------------------------------------------------------------
__global__ __launch_bounds__(256, 2)
void mma_gemm1(const float* __restrict__ A,
               const float* __restrict__ att_s, const float* __restrict__ att_d, int M) {
    __shared__ uint4 As_hi[512], As_lo[512];   // 128 rows x 4 chunks (16B)

    int tid = threadIdx.x;
    int lane = tid & 31, w = tid >> 5;
    int warp_m = w & 3, warp_n = w >> 2;
    int row0 = blockIdx.y * 128;
    int col0 = blockIdx.x * 128;

    uint32_t as_hi_b = (uint32_t)__cvta_generic_to_shared(As_hi);
    uint32_t as_lo_b = (uint32_t)__cvta_generic_to_shared(As_lo);

    const uint2* Wfh = (const uint2*)g_W1f_hi;
    const uint2* Wfl = (const uint2*)g_W1f_lo;
    int half16 = blockIdx.x * 16;              // fragment block for this col-half

    float C[2][8][4];
#pragma unroll
    for (int mt = 0; mt < 2; mt++)
#pragma unroll
        for (int nt = 0; nt < 8; nt++)
#pragma unroll
            for (int i = 0; i < 4; i++) C[mt][nt][i] = 0.f;

    int lr = lane & 15, lh = lane >> 4;

    for (int kc = 0; kc < 8; kc++) {
        int k0 = kc * 32;
        __syncthreads();
        // ---- A tile: load fp32, convert to bf16 hi/lo, swizzled store ----
#pragma unroll
        for (int j = 0; j < 2; j++) {
            int cid = j * 256 + tid;          // 0..511
            int row = cid >> 2;
            int ch  = cid & 3;
            int gr = row0 + row;
            float4 f0 = make_float4(0.f, 0.f, 0.f, 0.f), f1 = f0;
            if (gr < M) {
                const float4* p = (const float4*)(A + (size_t)gr * 256 + k0 + ch * 8);
                f0 = p[0]; f1 = p[1];
            }
            uint32_t h[4], l[4];
            split2(f0.x, f0.y, h[0], l[0]);
            split2(f0.z, f0.w, h[1], l[1]);
            split2(f1.x, f1.y, h[2], l[2]);
            split2(f1.z, f1.w, h[3], l[3]);
            int off = row * 4 + (ch ^ (row & 3));
            As_hi[off] = make_uint4(h[0], h[1], h[2], h[3]);
            As_lo[off] = make_uint4(l[0], l[1], l[2], l[3]);
        }
        __syncthreads();

#pragma unroll
        for (int ks = 0; ks < 2; ks++) {
            int kk2 = ks * 2;
            int blk = kc * 2 + ks;             // k16 block index (0..15)
            uint32_t a_hi[2][4], a_lo[2][4];
#pragma unroll
            for (int mt = 0; mt < 2; mt++) {
                int r = warp_m * 32 + mt * 16 + lr;
                int c = kk2 + lh;
                uint32_t bo = (uint32_t)(r * 4 + (c ^ (r & 3))) * 16;
                ldsm4(a_hi[mt], as_hi_b + bo);
                ldsm4(a_lo[mt], as_lo_b + bo);
            }
#pragma unroll
            for (int ng = 0; ng < 4; ng++) {
                int n8a = warp_n * 8 + ng * 2;       // two n8 fragments
                size_t f0 = ((size_t)(half16 + n8a) * 16 + blk) * 32 + lane;
                size_t f1 = f0 + 16 * 32;            // n8a+1
                uint2 bh0 = Wfh[f0], bh1 = Wfh[f1];
                uint2 bl0 = Wfl[f0], bl1 = Wfl[f1];
                uint32_t rbh0[2] = {bh0.x, bh0.y}, rbh1[2] = {bh1.x, bh1.y};
                uint32_t rbl0[2] = {bl0.x, bl0.y}, rbl1[2] = {bl1.x, bl1.y};
                int nt0 = ng * 2, nt1 = ng * 2 + 1;
#pragma unroll
                for (int mt = 0; mt < 2; mt++) {
                    mma16816(C[mt][nt0], a_hi[mt], rbh0);
                    mma16816(C[mt][nt0], a_hi[mt], rbl0);
                    mma16816(C[mt][nt0], a_lo[mt], rbh0);
                    mma16816(C[mt][nt1], a_hi[mt], rbh1);
                    mma16816(C[mt][nt1], a_hi[mt], rbl1);
                    mma16816(C[mt][nt1], a_lo[mt], rbh1);
                }
            }
        }
    }

    // ---- epilogue: store h1 + fused a1 projection ----
    int qr = lane >> 2, qc = lane & 3;
#pragma unroll
    for (int mt = 0; mt < 2; mt++) {
        int r = row0 + warp_m * 32 + mt * 16 + qr;
        float ps[2][2] = {{0.f, 0.f}, {0.f, 0.f}};  // [head_sel][row_inst]
        float pd[2][2] = {{0.f, 0.f}, {0.f, 0.f}};
#pragma unroll
        for (int nt = 0; nt < 8; nt++) {
            int cg = col0 + warp_n * 64 + nt * 8 + qc * 2;
            int hs = nt >> 2;
            float s0 = __ldg(att_s + cg), s1 = __ldg(att_s + cg + 1);
            float e0 = __ldg(att_d + cg), e1 = __ldg(att_d + cg + 1);
            ps[hs][0] += C[mt][nt][0] * s0 + C[mt][nt][1] * s1;
            pd[hs][0] += C[mt][nt][0] * e0 + C[mt][nt][1] * e1;
            ps[hs][1] += C[mt][nt][2] * s0 + C[mt][nt][3] * s1;
            pd[hs][1] += C[mt][nt][2] * e0 + C[mt][nt][3] * e1;
            if (r < M)
                *(float2*)(g_h1 + (size_t)r * 256 + cg) = make_float2(C[mt][nt][0], C[mt][nt][1]);
            if (r + 8 < M)
                *(float2*)(g_h1 + (size_t)(r + 8) * 256 + cg) = make_float2(C[mt][nt][2], C[mt][nt][3]);
        }
#pragma unroll
        for (int o = 1; o <= 2; o <<= 1) {
#pragma unroll
            for (int hs = 0; hs < 2; hs++)
#pragma unroll
                for (int ri = 0; ri < 2; ri++) {
                    ps[hs][ri] += __shfl_xor_sync(0xffffffffu, ps[hs][ri], o);
                    pd[hs][ri] += __shfl_xor_sync(0xffffffffu, pd[hs][ri], o);
                }
        }
        if (qc == 0) {
            int headb = (col0 >> 5) + warp_n * 2;
            if (r < M) {
                g_as1[r * 8 + headb]     = ps[0][0];
                g_as1[r * 8 + headb + 1] = ps[1][0];
                g_ad1[r * 8 + headb]     = pd[0][0];
                g_ad1[r * 8 + headb + 1] = pd[1][0];
            }
            if (r + 8 < M) {
                g_as1[(r + 8) * 8 + headb]     = ps[0][1];
                g_as1[(r + 8) * 8 + headb + 1] = ps[1][1];
                g_ad1[(r + 8) * 8 + headb]     = pd[0][1];
                g_ad1[(r + 8) * 8 + headb + 1] = pd[1][1];
            }
        }
    }
}

// ---------------------------------------------------------------------------
// CSR construction
// ---------------------------------------------------------------------------
__global__ void zero_deg(int M) {
    int i = blockIdx.x * blockDim.x + threadIdx.x;
    if (i < M) g_deg[i] = 0;
}

__global__ void count_deg(const int* __restrict__ dst, int E, int ET) {
    int e = blockIdx.x * blockDim.x + threadIdx.x;
    if (e >= ET) return;
    int d = (e < E) ? dst[e] : (e - E);
    atomicAdd(&g_deg[d], 1);
}

__global__ void scan_local(int M) {
    __shared__ int wsum[32];
    int b = blockIdx.x, tid = threadIdx.x, lane = tid & 31, w = tid >> 5;
    int i = b * 1024 + tid;
    int v = (i < M) ? g_deg[i] : 0;
    int x = v;
#pragma unroll
    for (int o = 1; o < 32; o <<= 1) {
        int y = __shfl_up_sync(0xffffffffu, x, o);
        if (lane >= o) x += y;
    }
    if (lane == 31) wsum[w] = x;
    __syncthreads();
    if (w == 0) {
        int s = wsum[lane];
#pragma unroll
        for (int o = 1; o < 32; o <<= 1) {
            int y = __shfl_up_sync(0xffffffffu, s, o);
            if (lane >= o) s += y;
        }
        wsum[lane] = s;
    }
    __syncthreads();
    int excl = (w > 0 ? wsum[w - 1] : 0) + x - v;
    if (i < M) g_rowptr[i] = excl;
    if (tid == 1023) g_btot[b] = wsum[31];
}

__global__ void scan_tops(int nb) {
    if (threadIdx.x == 0) {
        int s = 0;
        for (int j = 0; j < nb; j++) { g_boff[j] = s; s += g_btot[j]; }
    }
}

__global__ void add_off(int M) {
    int b = blockIdx.x;
    int i = b * 1024 + threadIdx.x;
    if (i < M) {
        int v = g_rowptr[i] + g_boff[b];
        g_rowptr[i] = v;
        g_cursor[i] = v;
    }
}

__global__ void scatter_csr(const int* __restrict__ src, const int* __restrict__ dst,
                            int E, int ET) {
    int e = blockIdx.x * blockDim.x + threadIdx.x;
    if (e >= ET) return;
    int s, d;
    if (e < E) { s = src[e]; d = dst[e]; } else { s = e - E; d = s; }
    int pos = atomicAdd(&g_cursor[d], 1);
    g_csr[pos] = s;
}

// ---------------------------------------------------------------------------
// Layer-1 fused: warp per dst node, channels in registers.
// BISECT CHANGE (only change vs R11): no-max softmax — plain exp, per-lane
// deferred denominator, zero per-chunk reductions, no acc rescaling.
// ---------------------------------------------------------------------------
__global__ __launch_bounds__(256)
void gat1_fused(const float* __restrict__ b1, int M) {
    __shared__ float s_w[8 * 256];
    int lane = threadIdx.x & 31, w = threadIdx.x >> 5;
    int node = blockIdx.x * 8 + w;
    if (node >= M) return;
    float* sw = s_w + w * 256;
    int hl = lane >> 2;

    float4 d0 = *(const float4*)(g_ad1 + (size_t)node * HH);
    float4 d1 = *(const float4*)(g_ad1 + (size_t)node * HH + 4);
    float adst[8] = {d0.x, d0.y, d0.z, d0.w, d1.x, d1.y, d1.z, d1.w};

    int start = g_rowptr[node];
    int deg   = g_deg[node];

    float den[8], acc[8];
#pragma unroll
    for (int h = 0; h < 8; h++) { den[h] = 0.f; acc[h] = 0.f; }

    for (int base = 0; base < deg; base += 32) {
        int nE = min(32, deg - base);
        int s = 0;
        float ex[8];
        if (lane < nE) {
            s = g_csr[start + base + lane];
            float4 a0 = *(const float4*)(g_as1 + (size_t)s * HH);
            float4 a1 = *(const float4*)(g_as1 + (size_t)s * HH + 4);
            float as[8] = {a0.x, a0.y, a0.z, a0.w, a1.x, a1.y, a1.z, a1.w};
#pragma unroll
            for (int h = 0; h < 8; h++) {
                float v = as[h] + adst[h];
                v = v > 0.f ? v : 0.2f * v;
                ex[h] = __expf(v);
            }
        } else {
#pragma unroll
            for (int h = 0; h < 8; h++) ex[h] = 0.f;
        }
#pragma unroll
        for (int h = 0; h < 8; h++) {
            den[h] += ex[h];
            sw[h * 32 + ((lane + h * 4) & 31)] = ex[h];
        }
        __syncwarp();

        const float* hbase = g_h1 + (size_t)lane * 8;
        int e = 0;
        for (; e + 4 <= nE; e += 4) {
            int s0 = __shfl_sync(0xffffffffu, s, e);
            int s1 = __shfl_sync(0xffffffffu, s, e + 1);
            int s2 = __shfl_sync(0xffffffffu, s, e + 2);
            int s3 = __shfl_sync(0xffffffffu, s, e + 3);
            float w0 = sw[hl * 32 + ((e     + hl * 4) & 31)];
            float w1 = sw[hl * 32 + ((e + 1 + hl * 4) & 31)];
            float w2 = sw[hl * 32 + ((e + 2 + hl * 4) & 31)];
            float w3 = sw[hl * 32 + ((e + 3 + hl * 4) & 31)];
            const float4* p0 = (const float4*)(hbase + (size_t)s0 * 256);
            const float4* p1 = (const float4*)(hbase + (size_t)s1 * 256);
            const float4* p2 = (const float4*)(hbase + (size_t)s2 * 256);
            const float4* p3 = (const float4*)(hbase + (size_t)s3 * 256);
            float4 u0 = p0[0], u1 = p0[1];
            float4 v0 = p1[0], v1 = p1[1];
            float4 x0 = p2[0], x1 = p2[1];
            float4 y0 = p3[0], y1 = p3[1];
            acc[0] += u0.x * w0 + v0.x * w1 + x0.x * w2 + y0.x * w3;
            acc[1] += u0.y * w0 + v0.y * w1 + x0.y * w2 + y0.y * w3;
            acc[2] += u0.z * w0 + v0.z * w1 + x0.z * w2 + y0.z * w3;
            acc[3] += u0.w * w0 + v0.w * w1 + x0.w * w2 + y0.w * w3;
            acc[4] += u1.x * w0 + v1.x * w1 + x1.x * w2 + y1.x * w3;
            acc[5] += u1.y * w0 + v1.y * w1 + x1.y * w2 + y1.y * w3;
            acc[6] += u1.z * w0 + v1.z * w1 + x1.z * w2 + y1.z * w3;
            acc[7] += u1.w * w0 + v1.w * w1 + x1.w * w2 + y1.w * w3;
        }
        for (; e < nE; e++) {
            int s0 = __shfl_sync(0xffffffffu, s, e);
            float w0 = sw[hl * 32 + ((e + hl * 4) & 31)];
            const float4* p0 = (const float4*)(hbase + (size_t)s0 * 256);
            float4 u0 = p0[0], u1 = p0[1];
            acc[0] += u0.x * w0; acc[1] += u0.y * w0;
            acc[2] += u0.z * w0; acc[3] += u0.w * w0;
            acc[4] += u1.x * w0; acc[5] += u1.y * w0;
            acc[6] += u1.z * w0; acc[7] += u1.w * w0;
        }
        __syncwarp();
    }

    // single deferred denominator reduction per node
#pragma unroll
    for (int h = 0; h < 8; h++) {
        float d = den[h];
#pragma unroll
        for (int o = 16; o > 0; o >>= 1)
            d += __shfl_xor_sync(0xffffffffu, d, o);
        den[h] = d;
    }
    float dsel = den[0];
#pragma unroll
    for (int h = 1; h < 8; h++) if (hl == h) dsel = den[h];
    float inv = 1.f / (dsel + 1e-16f);
    uint32_t oh[4], ol[4];
#pragma unroll
    for (int i = 0; i < 4; i++) {
        float o0 = acc[2 * i]     * inv + __ldg(b1 + lane * 8 + 2 * i);
        float o1 = acc[2 * i + 1] * inv + __ldg(b1 + lane * 8 + 2 * i + 1);
        o0 = o0 > 0.f ? o0 : expm1f(o0);
        o1 = o1 > 0.f ? o1 : expm1f(o1);
        split2(o0, o1, oh[i], ol[i]);
    }
    g_o1h[(size_t)node * 32 + lane] = make_uint4(oh[0], oh[1], oh[2], oh[3]);
    g_o1l[(size_t)node * 32 + lane] = make_uint4(ol[0], ol[1], ol[2], ol[3]);
}

// ---------------------------------------------------------------------------
// GEMM2 (tensor cores, register-only) + fused a2 projection
// ---------------------------------------------------------------------------
__global__ __launch_bounds__(256)
void mma_gemm2(const float* __restrict__ att_s, const float* __restrict__ att_d, int M) {
    int lane = threadIdx.x & 31, w = threadIdx.x >> 5;
    int g = lane >> 2, t = lane & 3;
    int rA  = blockIdx.x * 128 + w * 16 + g;
    int rA8 = rA + 8;
    int rAc  = min(rA,  M - 1);
    int rA8c = min(rA8, M - 1);

    const uint32_t* Ah = (const uint32_t*)g_o1h;
    const uint32_t* Al = (const uint32_t*)g_o1l;
    const uint32_t* p0h = Ah + (size_t)rAc  * 128 + t;
    const uint32_t* p1h = Ah + (size_t)rA8c * 128 + t;
    const uint32_t* p0l = Al + (size_t)rAc  * 128 + t;
    const uint32_t* p1l = Al + (size_t)rA8c * 128 + t;

    float C[5][4];
#pragma unroll
    for (int nt = 0; nt < 5; nt++)
#pragma unroll
        for (int i = 0; i < 4; i++) C[nt][i] = 0.f;

#pragma unroll
    for (int kk2 = 0; kk2 < 128; kk2 += 8) {
        uint32_t ah[4], al[4];
        ah[0] = p0h[kk2];     ah[1] = p1h[kk2];
        ah[2] = p0h[kk2 + 4]; ah[3] = p1h[kk2 + 4];
        al[0] = p0l[kk2];     al[1] = p1l[kk2];
        al[2] = p0l[kk2 + 4]; al[3] = p1l[kk2 + 4];
#pragma unroll
        for (int nt = 0; nt < 5; nt++) {
            int nb = (nt * 8 + g) * 128 + kk2 + t;
            uint32_t bh[2] = { g_W2t_hi[nb], g_W2t_hi[nb + 4] };
            uint32_t bl[2] = { g_W2t_lo[nb], g_W2t_lo[nb + 4] };
            mma16816(C[nt], ah, bh);
            mma16816(C[nt], ah, bl);
            mma16816(C[nt], al, bh);
        }
    }

    float ps0 = 0.f, pd0 = 0.f, ps1 = 0.f, pd1 = 0.f;
#pragma unroll
    for (int nt = 0; nt < 5; nt++) {
        int col = nt * 8 + t * 2;
        float s0 = __ldg(att_s + col), s1 = __ldg(att_s + col + 1);
        float e0 = __ldg(att_d + col), e1 = __ldg(att_d + col + 1);
        ps0 += C[nt][0] * s0 + C[nt][1] * s1;
        pd0 += C[nt][0] * e0 + C[nt][1] * e1;
        ps1 += C[nt][2] * s0 + C[nt][3] * s1;
        pd1 += C[nt][2] * e0 + C[nt][3] * e1;
        if (rA < M)
            *(float2*)(g_h2 + (size_t)rA * OUTC + col) = make_float2(C[nt][0], C[nt][1]);
        if (rA8 < M)
            *(float2*)(g_h2 + (size_t)rA8 * OUTC + col) = make_float2(C[nt][2], C[nt][3]);
    }
#pragma unroll
    for (int o = 1; o <= 2; o <<= 1) {
        ps0 += __shfl_xor_sync(0xffffffffu, ps0, o);
        pd0 += __shfl_xor_sync(0xffffffffu, pd0, o);
        ps1 += __shfl_xor_sync(0xffffffffu, ps1, o);
        pd1 += __shfl_xor_sync(0xffffffffu, pd1, o);
    }
    if (t == 0) {
        if (rA < M)  { g_as2[rA]  = ps0; g_ad2[rA]  = pd0; }
        if (rA8 < M) { g_as2[rA8] = ps1; g_ad2[rA8] = pd1; }
    }
}

// ---------------------------------------------------------------------------
// Layer-2 fused (no-max softmax, deferred denominator). Warp per dst node.
// (does NOT touch g_deg — zero_deg kernel retained, unlike R12)
// ---------------------------------------------------------------------------
__global__ __launch_bounds__(256)
void gat2_fused(float* __restrict__ out, const float* __restrict__ b2, int M) {
    int gw = (blockIdx.x * blockDim.x + threadIdx.x) >> 5;
    if (gw >= M) return;
    int lane = threadIdx.x & 31;

    int start = g_rowptr[gw];
    int deg   = g_deg[gw];
    float ad = g_ad2[gw];
    float den_l = 0.f, acc0 = 0.f, acc1 = 0.f;

    for (int base = 0; base < deg; base += 32) {
        int nE = min(32, deg - base);
        int s = 0;
        float ex = 0.f;
        if (lane < nE) {
            s = g_csr[start + base + lane];
            float t = g_as2[s] + ad;
            t = t > 0.f ? t : 0.2f * t;
            ex = __expf(t);
        }
        den_l += ex;
        for (int e = 0; e < nE; e++) {
            float a  = __shfl_sync(0xffffffffu, ex, e);
            int   se = __shfl_sync(0xffffffffu, s, e);
            const float* r = g_h2 + (size_t)se * OUTC;
            acc0 += r[lane] * a;
            if (lane < 8) acc1 += r[32 + lane] * a;
        }
    }
    float den = den_l;
#pragma unroll
    for (int o = 16; o > 0; o >>= 1)
        den += __shfl_xor_sync(0xffffffffu, den, o);
    float inv = 1.f / (den + 1e-16f);
    out[(size_t)gw * OUTC + lane] = acc0 * inv + __ldg(b2 + lane);
    if (lane < 8)
        out[(size_t)gw * OUTC + 32 + lane] = acc1 * inv + __ldg(b2 + 32 + lane);
}

// ---------------------------------------------------------------------------
// Launcher: EXACT R11 structure (fork-join, zero_deg retained, same order)
// ---------------------------------------------------------------------------
extern "C" void kernel_launch(void* const* d_in, const int* in_sizes, int n_in,
                              void* d_out, int out_size) {
    const float* x      = (const float*)d_in[0];
    const int*   ei     = (const int*)  d_in[1];
    const float* W1     = (const float*)d_in[2];
    const float* att_s1 = (const float*)d_in[3];
    const float* att_d1 = (const float*)d_in[4];
    const float* b1     = (const float*)d_in[5];
    const float* W2     = (const float*)d_in[6];
    const float* att_s2 = (const float*)d_in[7];
    const float* att_d2 = (const float*)d_in[8];
    const float* b2     = (const float*)d_in[9];
    float* out = (float*)d_out;

    int M  = in_sizes[0] / F1;
    int E  = in_sizes[1] / 2;
    int ET = E + M;
    int eb = (ET + 255) / 256;
    int nb = (M + 1023) / 1024;

    static cudaStream_t s2 = nullptr;
    static cudaEvent_t ev_fork = nullptr, ev_join = nullptr;
    if (s2 == nullptr) {
        cudaStreamCreateWithFlags(&s2, cudaStreamNonBlocking);
        cudaEventCreateWithFlags(&ev_fork, cudaEventDisableTiming);
        cudaEventCreateWithFlags(&ev_join, cudaEventDisableTiming);
    }

    // fork
    cudaEventRecord(ev_fork, 0);
    cudaStreamWaitEvent(s2, ev_fork, 0);

    // main stream: W1 prep + GEMM1 (the heavy compute)
    prep_W<<<128, 256>>>(W1);
    mma_gemm1<<<dim3(2, (M + 127) / 128), 256>>>(x, att_s1, att_d1, M);

    // side stream: CSR build + W2 prep (independent of GEMM1)
    zero_deg<<<(M + 255) / 256, 256, 0, s2>>>(M);
    count_deg<<<eb, 256, 0, s2>>>(ei + E, E, ET);
    scan_local<<<nb, 1024, 0, s2>>>(M);
    scan_tops<<<1, 32, 0, s2>>>(nb);
    add_off<<<nb, 1024, 0, s2>>>(M);
    scatter_csr<<<eb, 256, 0, s2>>>(ei, ei + E, E, ET);
    prep_W2<<<20, 256, 0, s2>>>(W2);
    cudaEventRecord(ev_join, s2);

    // join
    cudaStreamWaitEvent(0, ev_join, 0);

    // layer 1 edge phase + layer 2
    gat1_fused<<<(M + 7) / 8, 256>>>(b1, M);
    mma_gemm2<<<(M + 127) / 128, 256>>>(att_s2, att_d2, M);
    gat2_fused<<<(M * 32 + 255) / 256, 256>>>(out, b2, M);
}

// round 16
// speedup vs baseline: 1.3449x; 1.0543x over previous
#include <cuda_runtime.h>
#include <cuda_bf16.h>
#include <math.h>
#include <stdint.h>

// ---------------------------------------------------------------------------
// Problem constants
// ---------------------------------------------------------------------------
#define MAXN 100000
#define MAXE 800000
#define MAXET (MAXE + MAXN)
#define F1 256
#define HH 8
#define OUTC 40

// ---------------------------------------------------------------------------
// Scratch
// ---------------------------------------------------------------------------
__device__ float g_h1 [(size_t)MAXN * F1];     // x @ W1 (fp32, gathered in layer 1)
__device__ uint4 g_o1h[(size_t)MAXN * 32];     // out1 bf16 hi
__device__ uint4 g_o1l[(size_t)MAXN * 32];     // out1 bf16 lo
__device__ float g_h2 [(size_t)MAXN * OUTC];
__device__ float g_as1[MAXN * HH];
__device__ float g_ad1[MAXN * HH];
__device__ float g_as2[MAXN];
__device__ float g_ad2[MAXN];

// W1^T bf16 hi/lo, FRAGMENT-CONTIGUOUS layout:
// fragment f(ch, n8, k16) = 64 uint32 (256B); lane reads uint2 at frag+lane*8.
__device__ uint32_t g_W1f_hi[256 * 128];
__device__ uint32_t g_W1f_lo[256 * 128];
// W2^T bf16 hi/lo, [n=40][k2=128]
__device__ uint32_t g_W2t_hi[40 * 128];
__device__ uint32_t g_W2t_lo[40 * 128];

// CSR by destination
__device__ int g_deg   [MAXN];
__device__ int g_rowptr[MAXN];
__device__ int g_cursor[MAXN];
__device__ int g_csr   [MAXET];
__device__ int g_btot  [128];
__device__ int g_boff  [128];

// ---------------------------------------------------------------------------
// Helpers
// ---------------------------------------------------------------------------
__device__ __forceinline__ void split2(float a, float b, uint32_t& hi, uint32_t& lo) {
    __nv_bfloat16 ha = __float2bfloat16(a);
    __nv_bfloat16 hb = __float2bfloat16(b);
    __nv_bfloat16 la = __float2bfloat16(a - __bfloat162float(ha));
    __nv_bfloat16 lb = __float2bfloat16(b - __bfloat162float(hb));
    __nv_bfloat162 h = __halves2bfloat162(ha, hb);
    __nv_bfloat162 l = __halves2bfloat162(la, lb);
    hi = *reinterpret_cast<uint32_t*>(&h);
    lo = *reinterpret_cast<uint32_t*>(&l);
}

__device__ __forceinline__ void ldsm4(uint32_t* r, uint32_t addr) {
    asm volatile("ldmatrix.sync.aligned.m8n8.x4.shared.b16 {%0,%1,%2,%3}, [%4];"
        : "=r"(r[0]), "=r"(r[1]), "=r"(r[2]), "=r"(r[3]) : "r"(addr));
}

__device__ __forceinline__ void mma16816(float* c, const uint32_t* a, const uint32_t* b) {
    asm volatile(
        "mma.sync.aligned.m16n8k16.row.col.f32.bf16.bf16.f32 "
        "{%0,%1,%2,%3}, {%4,%5,%6,%7}, {%8,%9}, {%0,%1,%2,%3};\n"
        : "+f"(c[0]), "+f"(c[1]), "+f"(c[2]), "+f"(c[3])
        : "r"(a[0]), "r"(a[1]), "r"(a[2]), "r"(a[3]), "r"(b[0]), "r"(b[1]));
}

// ---------------------------------------------------------------------------
// Weight prep: W1 [k=256][n=256] -> fragment-contiguous bf16 hi/lo
// ---------------------------------------------------------------------------
__global__ void prep_W(const float* __restrict__ W) {
    int t = blockIdx.x * blockDim.x + threadIdx.x;
    if (t >= 256 * 128) return;
    int n = t >> 7, j = t & 127;            // n = output col, j = k2 index
    uint32_t h, l;
    split2(W[(size_t)(2 * j) * 256 + n], W[(size_t)(2 * j + 1) * 256 + n], h, l);
    int ch = n >> 7, nh = n & 127;
    int n8 = nh >> 3, ncol = nh & 7;
    int k16 = j >> 3, kp = (j >> 2) & 1, bt = j & 3;
    int lane = ncol * 4 + bt;
    int idx = (((ch * 16 + n8) * 16 + k16) * 32 + lane) * 2 + kp;
    g_W1f_hi[idx] = h;
    g_W1f_lo[idx] = l;
}

__global__ void prep_W2(const float* __restrict__ W2) {  // W2 [256][40]
    int t = blockIdx.x * blockDim.x + threadIdx.x;
    if (t >= 40 * 128) return;
    int n = t >> 7, k2 = t & 127, k = k2 * 2;
    uint32_t h, l;
    split2(W2[(size_t)k * OUTC + n], W2[(size_t)(k + 1) * OUTC + n], h, l);
    g_W2t_hi[n * 128 + k2] = h;
    g_W2t_lo[n * 128 + k2] = l;
}

// ---------------------------------------------------------------------------
// GEMM1 (tensor cores): g_h1[M,256] = x[M,256] @ W1[256,256], bf16 split.
// A through smem; B fragments direct from global, fragment-contiguous.
// Fused a1 projection in the epilogue. (ncu-verified 144us)
// ---------------------------------------------------------------------------
__global__ __launch_bounds__(256, 2)
void mma_gemm1(const float* __restrict__ A,
               const float* __restrict__ att_s, const float* __restrict__ att_d, int M) {
    __shared__ uint4 As_hi[512], As_lo[512];   // 128 rows x 4 chunks (16B)

    int tid = threadIdx.x;
    int lane = tid & 31, w = tid >> 5;
    int warp_m = w & 3, warp_n = w >> 2;
    int row0 = blockIdx.y * 128;
    int col0 = blockIdx.x * 128;

    uint32_t as_hi_b = (uint32_t)__cvta_generic_to_shared(As_hi);
    uint32_t as_lo_b = (uint32_t)__cvta_generic_to_shared(As_lo);

    const uint2* Wfh = (const uint2*)g_W1f_hi;
    const uint2* Wfl = (const uint2*)g_W1f_lo;
    int half16 = blockIdx.x * 16;              // fragment block for this col-half

    float C[2][8][4];
#pragma unroll
    for (int mt = 0; mt < 2; mt++)
#pragma unroll
        for (int nt = 0; nt < 8; nt++)
#pragma unroll
            for (int i = 0; i < 4; i++) C[mt][nt][i] = 0.f;

    int lr = lane & 15, lh = lane >> 4;

    for (int kc = 0; kc < 8; kc++) {
        int k0 = kc * 32;
        __syncthreads();
        // ---- A tile: load fp32, convert to bf16 hi/lo, swizzled store ----
#pragma unroll
        for (int j = 0; j < 2; j++) {
            int cid = j * 256 + tid;          // 0..511
            int row = cid >> 2;
            int ch  = cid & 3;
            int gr = row0 + row;
            float4 f0 = make_float4(0.f, 0.f, 0.f, 0.f), f1 = f0;
            if (gr < M) {
                const float4* p = (const float4*)(A + (size_t)gr * 256 + k0 + ch * 8);
                f0 = p[0]; f1 = p[1];
            }
            uint32_t h[4], l[4];
            split2(f0.x, f0.y, h[0], l[0]);
            split2(f0.z, f0.w, h[1], l[1]);
            split2(f1.x, f1.y, h[2], l[2]);
            split2(f1.z, f1.w, h[3], l[3]);
            int off = row * 4 + (ch ^ (row & 3));
            As_hi[off] = make_uint4(h[0], h[1], h[2], h[3]);
            As_lo[off] = make_uint4(l[0], l[1], l[2], l[3]);
        }
        __syncthreads();

#pragma unroll
        for (int ks = 0; ks < 2; ks++) {
            int kk2 = ks * 2;
            int blk = kc * 2 + ks;             // k16 block index (0..15)
            uint32_t a_hi[2][4], a_lo[2][4];
#pragma unroll
            for (int mt = 0; mt < 2; mt++) {
                int r = warp_m * 32 + mt * 16 + lr;
                int c = kk2 + lh;
                uint32_t bo = (uint32_t)(r * 4 + (c ^ (r & 3))) * 16;
                ldsm4(a_hi[mt], as_hi_b + bo);
                ldsm4(a_lo[mt], as_lo_b + bo);
            }
#pragma unroll
            for (int ng = 0; ng < 4; ng++) {
                int n8a = warp_n * 8 + ng * 2;       // two n8 fragments
                size_t f0 = ((size_t)(half16 + n8a) * 16 + blk) * 32 + lane;
                size_t f1 = f0 + 16 * 32;            // n8a+1
                uint2 bh0 = Wfh[f0], bh1 = Wfh[f1];
                uint2 bl0 = Wfl[f0], bl1 = Wfl[f1];
                uint32_t rbh0[2] = {bh0.x, bh0.y}, rbh1[2] = {bh1.x, bh1.y};
                uint32_t rbl0[2] = {bl0.x, bl0.y}, rbl1[2] = {bl1.x, bl1.y};
                int nt0 = ng * 2, nt1 = ng * 2 + 1;
#pragma unroll
                for (int mt = 0; mt < 2; mt++) {
                    mma16816(C[mt][nt0], a_hi[mt], rbh0);
                    mma16816(C[mt][nt0], a_hi[mt], rbl0);
                    mma16816(C[mt][nt0], a_lo[mt], rbh0);
                    mma16816(C[mt][nt1], a_hi[mt], rbh1);
                    mma16816(C[mt][nt1], a_hi[mt], rbl1);
                    mma16816(C[mt][nt1], a_lo[mt], rbh1);
                }
            }
        }
    }

    // ---- epilogue: store h1 + fused a1 projection ----
    int qr = lane >> 2, qc = lane & 3;
#pragma unroll
    for (int mt = 0; mt < 2; mt++) {
        int r = row0 + warp_m * 32 + mt * 16 + qr;
        float ps[2][2] = {{0.f, 0.f}, {0.f, 0.f}};  // [head_sel][row_inst]
        float pd[2][2] = {{0.f, 0.f}, {0.f, 0.f}};
#pragma unroll
        for (int nt = 0; nt < 8; nt++) {
            int cg = col0 + warp_n * 64 + nt * 8 + qc * 2;
            int hs = nt >> 2;
            float s0 = __ldg(att_s + cg), s1 = __ldg(att_s + cg + 1);
            float e0 = __ldg(att_d + cg), e1 = __ldg(att_d + cg + 1);
            ps[hs][0] += C[mt][nt][0] * s0 + C[mt][nt][1] * s1;
            pd[hs][0] += C[mt][nt][0] * e0 + C[mt][nt][1] * e1;
            ps[hs][1] += C[mt][nt][2] * s0 + C[mt][nt][3] * s1;
            pd[hs][1] += C[mt][nt][2] * e0 + C[mt][nt][3] * e1;
            if (r < M)
                *(float2*)(g_h1 + (size_t)r * 256 + cg) = make_float2(C[mt][nt][0], C[mt][nt][1]);
            if (r + 8 < M)
                *(float2*)(g_h1 + (size_t)(r + 8) * 256 + cg) = make_float2(C[mt][nt][2], C[mt][nt][3]);
        }
#pragma unroll
        for (int o = 1; o <= 2; o <<= 1) {
#pragma unroll
            for (int hs = 0; hs < 2; hs++)
#pragma unroll
                for (int ri = 0; ri < 2; ri++) {
                    ps[hs][ri] += __shfl_xor_sync(0xffffffffu, ps[hs][ri], o);
                    pd[hs][ri] += __shfl_xor_sync(0xffffffffu, pd[hs][ri], o);
                }
        }
        if (qc == 0) {
            int headb = (col0 >> 5) + warp_n * 2;
            if (r < M) {
                g_as1[r * 8 + headb]     = ps[0][0];
                g_as1[r * 8 + headb + 1] = ps[1][0];
                g_ad1[r * 8 + headb]     = pd[0][0];
                g_ad1[r * 8 + headb + 1] = pd[1][0];
            }
            if (r + 8 < M) {
                g_as1[(r + 8) * 8 + headb]     = ps[0][1];
                g_as1[(r + 8) * 8 + headb + 1] = ps[1][1];
                g_ad1[(r + 8) * 8 + headb]     = pd[0][1];
                g_ad1[(r + 8) * 8 + headb + 1] = pd[1][1];
            }
        }
    }
}

// ---------------------------------------------------------------------------
// CSR construction
// ---------------------------------------------------------------------------
__global__ void zero_deg(int M) {
    int i = blockIdx.x * blockDim.x + threadIdx.x;
    if (i < M) g_deg[i] = 0;
}

__global__ void count_deg(const int* __restrict__ dst, int E, int ET) {
    int e = blockIdx.x * blockDim.x + threadIdx.x;
    if (e >= ET) return;
    int d = (e < E) ? dst[e] : (e - E);
    atomicAdd(&g_deg[d], 1);
}

__global__ void scan_local(int M) {
    __shared__ int wsum[32];
    int b = blockIdx.x, tid = threadIdx.x, lane = tid & 31, w = tid >> 5;
    int i = b * 1024 + tid;
    int v = (i < M) ? g_deg[i] : 0;
    int x = v;
#pragma unroll
    for (int o = 1; o < 32; o <<= 1) {
        int y = __shfl_up_sync(0xffffffffu, x, o);
        if (lane >= o) x += y;
    }
    if (lane == 31) wsum[w] = x;
    __syncthreads();
    if (w == 0) {
        int s = wsum[lane];
#pragma unroll
        for (int o = 1; o < 32; o <<= 1) {
            int y = __shfl_up_sync(0xffffffffu, s, o);
            if (lane >= o) s += y;
        }
        wsum[lane] = s;
    }
    __syncthreads();
    int excl = (w > 0 ? wsum[w - 1] : 0) + x - v;
    if (i < M) g_rowptr[i] = excl;
    if (tid == 1023) g_btot[b] = wsum[31];
}

__global__ void scan_tops(int nb) {
    if (threadIdx.x == 0) {
        int s = 0;
        for (int j = 0; j < nb; j++) { g_boff[j] = s; s += g_btot[j]; }
    }
}

__global__ void add_off(int M) {
    int b = blockIdx.x;
    int i = b * 1024 + threadIdx.x;
    if (i < M) {
        int v = g_rowptr[i] + g_boff[b];
        g_rowptr[i] = v;
        g_cursor[i] = v;
    }
}

__global__ void scatter_csr(const int* __restrict__ src, const int* __restrict__ dst,
                            int E, int ET) {
    int e = blockIdx.x * blockDim.x + threadIdx.x;
    if (e >= ET) return;
    int s, d;
    if (e < E) { s = src[e]; d = dst[e]; } else { s = e - E; d = s; }
    int pos = atomicAdd(&g_cursor[d], 1);
    g_csr[pos] = s;
}

// ---------------------------------------------------------------------------
// Layer-1 fused: warp per dst node, no-max softmax (R15-verified), NEW:
// wavefront-efficient gather — lane owns channels [lane*4,+4) and
// [128+lane*4,+4), so each warp float4-load is 512B CONTIGUOUS (4 lines,
// not 8 half-lines). Exp weights in padded smem [edge][9] (9 coprime 32:
// conflict-free stores, broadcast reads).
// ---------------------------------------------------------------------------
__global__ __launch_bounds__(256)
void gat1_fused(const float* __restrict__ b1, int M) {
    __shared__ float s_w[8 * 288];            // 8 warps x 32 edges x 9 (pad)
    int lane = threadIdx.x & 31, w = threadIdx.x >> 5;
    int node = blockIdx.x * 8 + w;
    if (node >= M) return;
    float* sw = s_w + w * 288;
    int hA = lane >> 3;                       // head for channels lane*4..+3
    int cA = lane * 4;                        // first channel block
    int cB = 128 + lane * 4;                  // second channel block (head hA+4)

    float4 d0 = *(const float4*)(g_ad1 + (size_t)node * HH);
    float4 d1 = *(const float4*)(g_ad1 + (size_t)node * HH + 4);
    float adst[8] = {d0.x, d0.y, d0.z, d0.w, d1.x, d1.y, d1.z, d1.w};

    int start = g_rowptr[node];
    int deg   = g_deg[node];

    float den[8];
    float accA[4] = {0.f, 0.f, 0.f, 0.f};
    float accB[4] = {0.f, 0.f, 0.f, 0.f};
#pragma unroll
    for (int h = 0; h < 8; h++) den[h] = 0.f;

    for (int base = 0; base < deg; base += 32) {
        int nE = min(32, deg - base);
        int s = 0;
        float ex[8];
        if (lane < nE) {
            s = g_csr[start + base + lane];
            float4 a0 = *(const float4*)(g_as1 + (size_t)s * HH);
            float4 a1 = *(const float4*)(g_as1 + (size_t)s * HH + 4);
            float as[8] = {a0.x, a0.y, a0.z, a0.w, a1.x, a1.y, a1.z, a1.w};
#pragma unroll
            for (int h = 0; h < 8; h++) {
                float v = as[h] + adst[h];
                v = v > 0.f ? v : 0.2f * v;
                ex[h] = __expf(v);
            }
        } else {
#pragma unroll
            for (int h = 0; h < 8; h++) ex[h] = 0.f;
        }
#pragma unroll
        for (int h = 0; h < 8; h++) {
            den[h] += ex[h];
            sw[lane * 9 + h] = ex[h];
        }
        __syncwarp();

        const float* gA = g_h1 + cA;
        const float* gB = g_h1 + cB;
        int e = 0;
        for (; e + 4 <= nE; e += 4) {
            int s0 = __shfl_sync(0xffffffffu, s, e);
            int s1 = __shfl_sync(0xffffffffu, s, e + 1);
            int s2 = __shfl_sync(0xffffffffu, s, e + 2);
            int s3 = __shfl_sync(0xffffffffu, s, e + 3);
            float wA0 = sw[e * 9 + hA],           wB0 = sw[e * 9 + hA + 4];
            float wA1 = sw[(e + 1) * 9 + hA],     wB1 = sw[(e + 1) * 9 + hA + 4];
            float wA2 = sw[(e + 2) * 9 + hA],     wB2 = sw[(e + 2) * 9 + hA + 4];
            float wA3 = sw[(e + 3) * 9 + hA],     wB3 = sw[(e + 3) * 9 + hA + 4];
            float4 a0 = *(const float4*)(gA + (size_t)s0 * 256);
            float4 b0 = *(const float4*)(gB + (size_t)s0 * 256);
            float4 a1 = *(const float4*)(gA + (size_t)s1 * 256);
            float4 b1v = *(const float4*)(gB + (size_t)s1 * 256);
            float4 a2 = *(const float4*)(gA + (size_t)s2 * 256);
            float4 b2v = *(const float4*)(gB + (size_t)s2 * 256);
            float4 a3 = *(const float4*)(gA + (size_t)s3 * 256);
            float4 b3v = *(const float4*)(gB + (size_t)s3 * 256);
            accA[0] += a0.x * wA0 + a1.x * wA1 + a2.x * wA2 + a3.x * wA3;
            accA[1] += a0.y * wA0 + a1.y * wA1 + a2.y * wA2 + a3.y * wA3;
            accA[2] += a0.z * wA0 + a1.z * wA1 + a2.z * wA2 + a3.z * wA3;
            accA[3] += a0.w * wA0 + a1.w * wA1 + a2.w * wA2 + a3.w * wA3;
            accB[0] += b0.x * wB0 + b1v.x * wB1 + b2v.x * wB2 + b3v.x * wB3;
            accB[1] += b0.y * wB0 + b1v.y * wB1 + b2v.y * wB2 + b3v.y * wB3;
            accB[2] += b0.z * wB0 + b1v.z * wB1 + b2v.z * wB2 + b3v.z * wB3;
            accB[3] += b0.w * wB0 + b1v.w * wB1 + b2v.w * wB2 + b3v.w * wB3;
        }
        for (; e < nE; e++) {
            int s0 = __shfl_sync(0xffffffffu, s, e);
            float wA0 = sw[e * 9 + hA], wB0 = sw[e * 9 + hA + 4];
            float4 a0 = *(const float4*)(gA + (size_t)s0 * 256);
            float4 b0 = *(const float4*)(gB + (size_t)s0 * 256);
            accA[0] += a0.x * wA0; accA[1] += a0.y * wA0;
            accA[2] += a0.z * wA0; accA[3] += a0.w * wA0;
            accB[0] += b0.x * wB0; accB[1] += b0.y * wB0;
            accB[2] += b0.z * wB0; accB[3] += b0.w * wB0;
        }
        __syncwarp();
    }

    // single deferred denominator reduction per node
#pragma unroll
    for (int h = 0; h < 8; h++) {
        float d = den[h];
#pragma unroll
        for (int o = 16; o > 0; o >>= 1)
            d += __shfl_xor_sync(0xffffffffu, d, o);
        den[h] = d;
    }
    float dA = den[0], dB = den[4];
#pragma unroll
    for (int h = 1; h < 4; h++)
        if (hA == h) { dA = den[h]; dB = den[h + 4]; }
    float invA = 1.f / (dA + 1e-16f);
    float invB = 1.f / (dB + 1e-16f);

    uint32_t ohA[2], olA[2], ohB[2], olB[2];
#pragma unroll
    for (int i = 0; i < 2; i++) {
        float a0 = accA[2 * i]     * invA + __ldg(b1 + cA + 2 * i);
        float a1 = accA[2 * i + 1] * invA + __ldg(b1 + cA + 2 * i + 1);
        float q0 = accB[2 * i]     * invB + __ldg(b1 + cB + 2 * i);
        float q1 = accB[2 * i + 1] * invB + __ldg(b1 + cB + 2 * i + 1);
        a0 = a0 > 0.f ? a0 : expm1f(a0);
        a1 = a1 > 0.f ? a1 : expm1f(a1);
        q0 = q0 > 0.f ? q0 : expm1f(q0);
        q1 = q1 > 0.f ? q1 : expm1f(q1);
        split2(a0, a1, ohA[i], olA[i]);
        split2(q0, q1, ohB[i], olB[i]);
    }
    // channel-ordered layout identical to before: uint2 j covers channels 4j..4j+3
    uint2* o1h = (uint2*)g_o1h;
    uint2* o1l = (uint2*)g_o1l;
    o1h[(size_t)node * 64 + lane]      = make_uint2(ohA[0], ohA[1]);
    o1h[(size_t)node * 64 + 32 + lane] = make_uint2(ohB[0], ohB[1]);
    o1l[(size_t)node * 64 + lane]      = make_uint2(olA[0], olA[1]);
    o1l[(size_t)node * 64 + 32 + lane] = make_uint2(olB[0], olB[1]);
}

// ---------------------------------------------------------------------------
// GEMM2 (tensor cores, register-only) + fused a2 projection
// ---------------------------------------------------------------------------
__global__ __launch_bounds__(256)
void mma_gemm2(const float* __restrict__ att_s, const float* __restrict__ att_d, int M) {
    int lane = threadIdx.x & 31, w = threadIdx.x >> 5;
    int g = lane >> 2, t = lane & 3;
    int rA  = blockIdx.x * 128 + w * 16 + g;
    int rA8 = rA + 8;
    int rAc  = min(rA,  M - 1);
    int rA8c = min(rA8, M - 1);

    const uint32_t* Ah = (const uint32_t*)g_o1h;
    const uint32_t* Al = (const uint32_t*)g_o1l;
    const uint32_t* p0h = Ah + (size_t)rAc  * 128 + t;
    const uint32_t* p1h = Ah + (size_t)rA8c * 128 + t;
    const uint32_t* p0l = Al + (size_t)rAc  * 128 + t;
    const uint32_t* p1l = Al + (size_t)rA8c * 128 + t;

    float C[5][4];
#pragma unroll
    for (int nt = 0; nt < 5; nt++)
#pragma unroll
        for (int i = 0; i < 4; i++) C[nt][i] = 0.f;

#pragma unroll
    for (int kk2 = 0; kk2 < 128; kk2 += 8) {
        uint32_t ah[4], al[4];
        ah[0] = p0h[kk2];     ah[1] = p1h[kk2];
        ah[2] = p0h[kk2 + 4]; ah[3] = p1h[kk2 + 4];
        al[0] = p0l[kk2];     al[1] = p1l[kk2];
        al[2] = p0l[kk2 + 4]; al[3] = p1l[kk2 + 4];
#pragma unroll
        for (int nt = 0; nt < 5; nt++) {
            int nb = (nt * 8 + g) * 128 + kk2 + t;
            uint32_t bh[2] = { g_W2t_hi[nb], g_W2t_hi[nb + 4] };
            uint32_t bl[2] = { g_W2t_lo[nb], g_W2t_lo[nb + 4] };
            mma16816(C[nt], ah, bh);
            mma16816(C[nt], ah, bl);
            mma16816(C[nt], al, bh);
        }
    }

    float ps0 = 0.f, pd0 = 0.f, ps1 = 0.f, pd1 = 0.f;
#pragma unroll
    for (int nt = 0; nt < 5; nt++) {
        int col = nt * 8 + t * 2;
        float s0 = __ldg(att_s + col), s1 = __ldg(att_s + col + 1);
        float e0 = __ldg(att_d + col), e1 = __ldg(att_d + col + 1);
        ps0 += C[nt][0] * s0 + C[nt][1] * s1;
        pd0 += C[nt][0] * e0 + C[nt][1] * e1;
        ps1 += C[nt][2] * s0 + C[nt][3] * s1;
        pd1 += C[nt][2] * e0 + C[nt][3] * e1;
        if (rA < M)
            *(float2*)(g_h2 + (size_t)rA * OUTC + col) = make_float2(C[nt][0], C[nt][1]);
        if (rA8 < M)
            *(float2*)(g_h2 + (size_t)rA8 * OUTC + col) = make_float2(C[nt][2], C[nt][3]);
    }
#pragma unroll
    for (int o = 1; o <= 2; o <<= 1) {
        ps0 += __shfl_xor_sync(0xffffffffu, ps0, o);
        pd0 += __shfl_xor_sync(0xffffffffu, pd0, o);
        ps1 += __shfl_xor_sync(0xffffffffu, ps1, o);
        pd1 += __shfl_xor_sync(0xffffffffu, pd1, o);
    }
    if (t == 0) {
        if (rA < M)  { g_as2[rA]  = ps0; g_ad2[rA]  = pd0; }
        if (rA8 < M) { g_as2[rA8] = ps1; g_ad2[rA8] = pd1; }
    }
}

// ---------------------------------------------------------------------------
// Layer-2 fused (no-max softmax, deferred denominator). Warp per dst node.
// ---------------------------------------------------------------------------
__global__ __launch_bounds__(256)
void gat2_fused(float* __restrict__ out, const float* __restrict__ b2, int M) {
    int gw = (blockIdx.x * blockDim.x + threadIdx.x) >> 5;
    if (gw >= M) return;
    int lane = threadIdx.x & 31;

    int start = g_rowptr[gw];
    int deg   = g_deg[gw];
    float ad = g_ad2[gw];
    float den_l = 0.f, acc0 = 0.f, acc1 = 0.f;

    for (int base = 0; base < deg; base += 32) {
        int nE = min(32, deg - base);
        int s = 0;
        float ex = 0.f;
        if (lane < nE) {
            s = g_csr[start + base + lane];
            float t = g_as2[s] + ad;
            t = t > 0.f ? t : 0.2f * t;
            ex = __expf(t);
        }
        den_l += ex;
        for (int e = 0; e < nE; e++) {
            float a  = __shfl_sync(0xffffffffu, ex, e);
            int   se = __shfl_sync(0xffffffffu, s, e);
            const float* r = g_h2 + (size_t)se * OUTC;
            acc0 += r[lane] * a;
            if (lane < 8) acc1 += r[32 + lane] * a;
        }
    }
    float den = den_l;
#pragma unroll
    for (int o = 16; o > 0; o >>= 1)
        den += __shfl_xor_sync(0xffffffffu, den, o);
    float inv = 1.f / (den + 1e-16f);
    out[(size_t)gw * OUTC + lane] = acc0 * inv + __ldg(b2 + lane);
    if (lane < 8)
        out[(size_t)gw * OUTC + 32 + lane] = acc1 * inv + __ldg(b2 + 32 + lane);
}

// ---------------------------------------------------------------------------
// Launcher: EXACT R11/R15 structure (fork-join, zero_deg retained, same order)
// ---------------------------------------------------------------------------
extern "C" void kernel_launch(void* const* d_in, const int* in_sizes, int n_in,
                              void* d_out, int out_size) {
    const float* x      = (const float*)d_in[0];
    const int*   ei     = (const int*)  d_in[1];
    const float* W1     = (const float*)d_in[2];
    const float* att_s1 = (const float*)d_in[3];
    const float* att_d1 = (const float*)d_in[4];
    const float* b1     = (const float*)d_in[5];
    const float* W2     = (const float*)d_in[6];
    const float* att_s2 = (const float*)d_in[7];
    const float* att_d2 = (const float*)d_in[8];
    const float* b2     = (const float*)d_in[9];
    float* out = (float*)d_out;

    int M  = in_sizes[0] / F1;
    int E  = in_sizes[1] / 2;
    int ET = E + M;
    int eb = (ET + 255) / 256;
    int nb = (M + 1023) / 1024;

    static cudaStream_t s2 = nullptr;
    static cudaEvent_t ev_fork = nullptr, ev_join = nullptr;
    if (s2 == nullptr) {
        cudaStreamCreateWithFlags(&s2, cudaStreamNonBlocking);
        cudaEventCreateWithFlags(&ev_fork, cudaEventDisableTiming);
        cudaEventCreateWithFlags(&ev_join, cudaEventDisableTiming);
    }

    // fork
    cudaEventRecord(ev_fork, 0);
    cudaStreamWaitEvent(s2, ev_fork, 0);

    // main stream: W1 prep + GEMM1 (the heavy compute)
    prep_W<<<128, 256>>>(W1);
    mma_gemm1<<<dim3(2, (M + 127) / 128), 256>>>(x, att_s1, att_d1, M);

    // side stream: CSR build + W2 prep (independent of GEMM1)
    zero_deg<<<(M + 255) / 256, 256, 0, s2>>>(M);
    count_deg<<<eb, 256, 0, s2>>>(ei + E, E, ET);
    scan_local<<<nb, 1024, 0, s2>>>(M);
    scan_tops<<<1, 32, 0, s2>>>(nb);
    add_off<<<nb, 1024, 0, s2>>>(M);
    scatter_csr<<<eb, 256, 0, s2>>>(ei, ei + E, E, ET);
    prep_W2<<<20, 256, 0, s2>>>(W2);
    cudaEventRecord(ev_join, s2);

    // join
    cudaStreamWaitEvent(0, ev_join, 0);

    // layer 1 edge phase + layer 2
    gat1_fused<<<(M + 7) / 8, 256>>>(b1, M);
    mma_gemm2<<<(M + 127) / 128, 256>>>(att_s2, att_d2, M);
    gat2_fused<<<(M * 32 + 255) / 256, 256>>>(out, b2, M);
}